// round 1
// baseline (speedup 1.0000x reference)
#include <cuda_runtime.h>

// Problem dims (fixed by the dataset)
#define BB    8
#define NTOK  2048
#define LOW   512
#define HIGH  4096

// ---------------- scratch (static device memory; no allocs allowed) -------
__device__ float g_Q[(size_t)BB * NTOK * LOW];    //  32 MB
__device__ float g_K[(size_t)BB * NTOK * HIGH];   // 256 MB
__device__ float g_V[(size_t)BB * NTOK * LOW];    //  32 MB
__device__ float g_E[(size_t)BB * LOW * HIGH];    //  64 MB (scores -> combined attn, in place)
__device__ float g_X[(size_t)BB * NTOK * HIGH];   // 256 MB

// ---------------- generic tiled SGEMM -------------------------------------
// MODE 0 (NN): C[m,n] = sum_k A[m*lda+k] * B[k*ldb+n]
// MODE 1 (NT): C[m,n] = sum_k A[m*lda+k] * B[n*ldb+k]
// MODE 2 (TN): C[m,n] = sum_k A[k*lda+m] * B[k*ldb+n]
// C = alpha * (A op B) + bias[n]   (bias may be null)
// All of M, N multiples of 128; K multiple of 16; pointers 16B-aligned.
#define GBM 128
#define GBN 128
#define GBK 16

template <int MODE>
__global__ __launch_bounds__(256) void gemm_kernel(
    int M, int N, int K,
    const float* __restrict__ A, int lda, long long strideA,
    const float* __restrict__ B, int ldb, long long strideB,
    float* __restrict__ C, int ldc, long long strideC,
    const float* __restrict__ bias, float alpha)
{
    __shared__ float As[GBK][GBM + 4];
    __shared__ float Bs[GBK][GBN + 4];

    const int bz = blockIdx.z;
    A += (long long)bz * strideA;
    B += (long long)bz * strideB;
    C += (long long)bz * strideC;

    const int tid = threadIdx.x;
    const int tx = tid & 15;        // 0..15 -> n microtile
    const int ty = tid >> 4;        // 0..15 -> m microtile
    const int m0 = blockIdx.y * GBM;
    const int n0 = blockIdx.x * GBN;

    float acc[8][8];
#pragma unroll
    for (int i = 0; i < 8; i++)
#pragma unroll
        for (int j = 0; j < 8; j++) acc[i][j] = 0.f;

    for (int k0 = 0; k0 < K; k0 += GBK) {
        // ---- load A tile into As[k][m] ----
        if (MODE == 2) {
            // A is [K, M]: contiguous along m
#pragma unroll
            for (int r = 0; r < 2; r++) {
                int i = tid + r * 256;
                int k = i >> 5;                 // 0..15
                int m4 = (i & 31) << 2;         // 0..124
                float4 v = *(const float4*)&A[(long long)(k0 + k) * lda + m0 + m4];
                *(float4*)&As[k][m4] = v;
            }
        } else {
            // A is [M, K]: contiguous along k, transpose into shared
#pragma unroll
            for (int r = 0; r < 2; r++) {
                int i = tid + r * 256;
                int m = i >> 2;                 // 0..127
                int k4 = (i & 3) << 2;          // 0,4,8,12
                float4 v = *(const float4*)&A[(long long)(m0 + m) * lda + k0 + k4];
                As[k4 + 0][m] = v.x;
                As[k4 + 1][m] = v.y;
                As[k4 + 2][m] = v.z;
                As[k4 + 3][m] = v.w;
            }
        }
        // ---- load B tile into Bs[k][n] ----
        if (MODE == 1) {
            // B is [N, K]: contiguous along k, transpose
#pragma unroll
            for (int r = 0; r < 2; r++) {
                int i = tid + r * 256;
                int n = i >> 2;
                int k4 = (i & 3) << 2;
                float4 v = *(const float4*)&B[(long long)(n0 + n) * ldb + k0 + k4];
                Bs[k4 + 0][n] = v.x;
                Bs[k4 + 1][n] = v.y;
                Bs[k4 + 2][n] = v.z;
                Bs[k4 + 3][n] = v.w;
            }
        } else {
            // B is [K, N]: contiguous along n
#pragma unroll
            for (int r = 0; r < 2; r++) {
                int i = tid + r * 256;
                int k = i >> 5;
                int n4 = (i & 31) << 2;
                float4 v = *(const float4*)&B[(long long)(k0 + k) * ldb + n0 + n4];
                *(float4*)&Bs[k][n4] = v;
            }
        }
        __syncthreads();

#pragma unroll
        for (int k = 0; k < GBK; k++) {
            float4 a0 = *(const float4*)&As[k][ty * 8];
            float4 a1 = *(const float4*)&As[k][ty * 8 + 4];
            float4 b0 = *(const float4*)&Bs[k][tx * 8];
            float4 b1 = *(const float4*)&Bs[k][tx * 8 + 4];
            float a[8] = {a0.x, a0.y, a0.z, a0.w, a1.x, a1.y, a1.z, a1.w};
            float b[8] = {b0.x, b0.y, b0.z, b0.w, b1.x, b1.y, b1.z, b1.w};
#pragma unroll
            for (int i = 0; i < 8; i++)
#pragma unroll
                for (int j = 0; j < 8; j++) acc[i][j] = fmaf(a[i], b[j], acc[i][j]);
        }
        __syncthreads();
    }

    // ---- epilogue ----
    float bv[8];
#pragma unroll
    for (int j = 0; j < 8; j++) bv[j] = bias ? bias[n0 + tx * 8 + j] : 0.f;
#pragma unroll
    for (int i = 0; i < 8; i++) {
        long long row = (long long)(m0 + ty * 8 + i) * ldc + n0 + tx * 8;
#pragma unroll
        for (int j = 0; j < 8; j++) {
            C[row + j] = acc[i][j] * alpha + bv[j];
        }
    }
}

// ---------------- combined softmax(e) + softmax(minmaxnorm(e,mask)) --------
// One block per (b, l) row of HIGH=4096 scores. Writes, in place,
//   A[h] = softmax_global(e)[h] + (mask[h] ? softmax_local(minmaxnorm(e))[h] : 0)
__device__ __forceinline__ float warpMax(float v) {
#pragma unroll
    for (int o = 16; o > 0; o >>= 1) v = fmaxf(v, __shfl_xor_sync(0xffffffffu, v, o));
    return v;
}
__device__ __forceinline__ float warpMin(float v) {
#pragma unroll
    for (int o = 16; o > 0; o >>= 1) v = fminf(v, __shfl_xor_sync(0xffffffffu, v, o));
    return v;
}
__device__ __forceinline__ float warpSum(float v) {
#pragma unroll
    for (int o = 16; o > 0; o >>= 1) v += __shfl_xor_sync(0xffffffffu, v, o);
    return v;
}

__global__ __launch_bounds__(256) void attn_combine_kernel(
    float* __restrict__ E, const int* __restrict__ linkage)
{
    const int H = HIGH;
    const int l = blockIdx.x;
    const int b = blockIdx.y;
    float* row = E + ((long long)b * LOW + l) * H;
    const int* mrow = linkage + (long long)l * H;

    __shared__ float se[HIGH];
    __shared__ unsigned char sm[HIGH];
    __shared__ float bufg[8], bufn[8], bufx[8], bufs1[8], bufs2[8];

    const int tid = threadIdx.x;
    const int lane = tid & 31, wid = tid >> 5;
    const float BIGV = 9.0e15f;

    float gmax = -3.0e38f, mn = BIGV, mx = -BIGV;
    for (int h = tid; h < H; h += 256) {
        float v = row[h];
        int m = mrow[h];
        se[h] = v;
        sm[h] = (unsigned char)(m > 0);
        gmax = fmaxf(gmax, v);
        if (m > 0) { mn = fminf(mn, v); mx = fmaxf(mx, v); }
    }
    gmax = warpMax(gmax); mn = warpMin(mn); mx = warpMax(mx);
    if (lane == 0) { bufg[wid] = gmax; bufn[wid] = mn; bufx[wid] = mx; }
    __syncthreads();
    float GM = bufg[0], MN = bufn[0], MX = bufx[0];
#pragma unroll
    for (int i = 1; i < 8; i++) {
        GM = fmaxf(GM, bufg[i]); MN = fminf(MN, bufn[i]); MX = fmaxf(MX, bufx[i]);
    }

    float den = MX - MN;
    if (den == 0.f) den = 1e-6f;
    const float rden = 1.f / den;
    const float lmax = (MX - MN) * rden;   // analytic max of normalized masked scores

    float gsum = 0.f, lsum = 0.f;
    for (int h = tid; h < H; h += 256) {
        float v = se[h];
        gsum += __expf(v - GM);
        if (sm[h]) lsum += __expf((v - MN) * rden - lmax);
    }
    gsum = warpSum(gsum); lsum = warpSum(lsum);
    if (lane == 0) { bufs1[wid] = gsum; bufs2[wid] = lsum; }
    __syncthreads();
    float GS = 0.f, LS = 0.f;
#pragma unroll
    for (int i = 0; i < 8; i++) { GS += bufs1[i]; LS += bufs2[i]; }
    const float rg = 1.f / GS, rl = 1.f / LS;

    for (int h = tid; h < H; h += 256) {
        float v = se[h];
        float o = __expf(v - GM) * rg;
        if (sm[h]) o += __expf((v - MN) * rden - lmax) * rl;
        row[h] = o;
    }
}

// ---------------- launch ----------------------------------------------------
extern "C" void kernel_launch(void* const* d_in, const int* in_sizes, int n_in,
                              void* d_out, int out_size)
{
    const float* x     = (const float*)d_in[0];
    const int*   link  = (const int*)  d_in[1];
    const float* wq_w  = (const float*)d_in[2];
    const float* wq_b  = (const float*)d_in[3];
    const float* wk_w  = (const float*)d_in[4];
    const float* wk_b  = (const float*)d_in[5];
    const float* wv_w  = (const float*)d_in[6];
    const float* wv_b  = (const float*)d_in[7];
    const float* o_w   = (const float*)d_in[8];
    const float* o_b   = (const float*)d_in[9];
    float* out = (float*)d_out;

    float *Q, *Km, *V, *E, *X;
    cudaGetSymbolAddress((void**)&Q,  g_Q);
    cudaGetSymbolAddress((void**)&Km, g_K);
    cudaGetSymbolAddress((void**)&V,  g_V);
    cudaGetSymbolAddress((void**)&E,  g_E);
    cudaGetSymbolAddress((void**)&X,  g_X);

    const int MT = BB * NTOK;     // 16384 flattened tokens
    dim3 blk(256);

    // Q = x @ wq_w^T + wq_b           [16384, 512]
    gemm_kernel<1><<<dim3(LOW / 128, MT / 128, 1), blk>>>(
        MT, LOW, LOW, x, LOW, 0, wq_w, LOW, 0, Q, LOW, 0, wq_b, 1.f);
    // K = x @ wk_w^T + wk_b           [16384, 4096]
    gemm_kernel<1><<<dim3(HIGH / 128, MT / 128, 1), blk>>>(
        MT, HIGH, LOW, x, LOW, 0, wk_w, LOW, 0, Km, HIGH, 0, wk_b, 1.f);
    // V = x @ wv_w^T + wv_b           [16384, 512]
    gemm_kernel<1><<<dim3(LOW / 128, MT / 128, 1), blk>>>(
        MT, LOW, LOW, x, LOW, 0, wv_w, LOW, 0, V, LOW, 0, wv_b, 1.f);

    // e[b] = Q[b]^T @ K[b] / 64       [8, 512, 4096]  (TN, batched over b)
    gemm_kernel<2><<<dim3(HIGH / 128, LOW / 128, BB), blk>>>(
        LOW, HIGH, NTOK,
        Q, LOW, (long long)NTOK * LOW,
        Km, HIGH, (long long)NTOK * HIGH,
        E, HIGH, (long long)LOW * HIGH,
        nullptr, 0.015625f);

    // E <- softmax_global(E) + softmax_local(minmaxnorm(E, mask))  (in place)
    attn_combine_kernel<<<dim3(LOW, BB), 256>>>(E, link);

    // x[b] = V[b] @ E[b]              [8, 2048, 4096]  (NN, batched)
    gemm_kernel<0><<<dim3(HIGH / 128, NTOK / 128, BB), blk>>>(
        NTOK, HIGH, LOW,
        V, LOW, (long long)NTOK * LOW,
        E, HIGH, (long long)LOW * HIGH,
        X, HIGH, (long long)NTOK * HIGH,
        nullptr, 1.f);

    // out = x @ o_w^T + o_b           [16384, 4096]
    gemm_kernel<1><<<dim3(HIGH / 128, MT / 128, 1), blk>>>(
        MT, HIGH, HIGH, X, HIGH, 0, o_w, HIGH, 0, out, HIGH, 0, o_b, 1.f);
}

// round 3
// speedup vs baseline: 3.1959x; 3.1959x over previous
#include <cuda_runtime.h>
#include <cstdint>

#define BB    8
#define NTOK  2048
#define LOW   512
#define HIGH  4096

// ---------------- scratch (static device memory; no allocs allowed) -------
__device__ float g_Q[(size_t)BB * NTOK * LOW];
__device__ float g_K[(size_t)BB * NTOK * HIGH];
__device__ float g_V[(size_t)BB * NTOK * LOW];
__device__ float g_E[(size_t)BB * LOW * HIGH];
__device__ float g_X[(size_t)BB * NTOK * HIGH];

// ---------------- helpers ---------------------------------------------------
__device__ __forceinline__ uint32_t smem_u32(const void* p) {
    return (uint32_t)__cvta_generic_to_shared(p);
}
__device__ __forceinline__ void cp16(uint32_t s, const void* g) {
    asm volatile("cp.async.cg.shared.global [%0], [%1], 16;" :: "r"(s), "l"(g));
}
__device__ __forceinline__ void cp_commit() {
    asm volatile("cp.async.commit_group;" ::: "memory");
}
template <int N>
__device__ __forceinline__ void cp_wait() {
    asm volatile("cp.async.wait_group %0;" :: "n"(N) : "memory");
}
__device__ __forceinline__ uint32_t to_tf32(float f) {
    uint32_t r;
    asm("cvt.rna.tf32.f32 %0, %1;" : "=r"(r) : "f"(f));
    return r;
}

// ---------------- tf32 tensor-core GEMM -------------------------------------
// C[m,n] = alpha * sum_k A(m,k) * B(n,k) + bias[n]
// MODE 0: operand stored [dim, K] (k contiguous)  -> smem [dim][k], stride 20
// MODE 1: operand stored [K, dim] (dim contiguous)-> smem [k][dim], stride 136
#define Bb   128
#define BK   16

template <int AMODE, int BMODE>
__global__ __launch_bounds__(256) void gemm_tc(
    int M, int N, int K,
    const float* __restrict__ A, int lda, long long strideA,
    const float* __restrict__ B, int ldb, long long strideB,
    float* __restrict__ C, int ldc, long long strideC,
    const float* __restrict__ bias, float alpha)
{
    constexpr int ASTR = AMODE ? 136 : 20;
    constexpr int BSTR = BMODE ? 136 : 20;
    constexpr int AFL = AMODE ? (BK * 136) : (Bb * 20);
    constexpr int BFL = BMODE ? (BK * 136) : (Bb * 20);

    __shared__ float sA[2][AFL];
    __shared__ float sB[2][BFL];

    const int tid = threadIdx.x;
    const int wid = tid >> 5;
    const int lane = tid & 31;
    const int g = lane >> 2;      // group id 0..7
    const int t = lane & 3;       // thread-in-group 0..3
    const int warp_m = wid & 1;   // 2 warps over M
    const int warp_n = wid >> 1;  // 4 warps over N

    A += (long long)blockIdx.z * strideA;
    B += (long long)blockIdx.z * strideB;
    C += (long long)blockIdx.z * strideC;
    const int m0 = blockIdx.y * Bb;
    const int n0 = blockIdx.x * Bb;

    // ---- async tile loaders (each thread moves 2 chunks of 16B per operand)
    auto loadA = [&](int buf, int k0) {
        uint32_t s0 = smem_u32(&sA[buf][0]);
#pragma unroll
        for (int r = 0; r < 2; r++) {
            int i = tid + r * 256;
            if (AMODE == 0) {
                int row = i >> 2, kq = i & 3;
                cp16(s0 + (uint32_t)(row * 80 + kq * 16),
                     &A[(long long)(m0 + row) * lda + k0 + kq * 4]);
            } else {
                int k = i >> 5, dq = i & 31;
                cp16(s0 + (uint32_t)(k * 544 + dq * 16),
                     &A[(long long)(k0 + k) * lda + m0 + dq * 4]);
            }
        }
    };
    auto loadB = [&](int buf, int k0) {
        uint32_t s0 = smem_u32(&sB[buf][0]);
#pragma unroll
        for (int r = 0; r < 2; r++) {
            int i = tid + r * 256;
            if (BMODE == 0) {
                int row = i >> 2, kq = i & 3;
                cp16(s0 + (uint32_t)(row * 80 + kq * 16),
                     &B[(long long)(n0 + row) * ldb + k0 + kq * 4]);
            } else {
                int k = i >> 5, dq = i & 31;
                cp16(s0 + (uint32_t)(k * 544 + dq * 16),
                     &B[(long long)(k0 + k) * ldb + n0 + dq * 4]);
            }
        }
    };

    float acc[4][4][4];
#pragma unroll
    for (int i = 0; i < 4; i++)
#pragma unroll
        for (int j = 0; j < 4; j++)
#pragma unroll
            for (int r = 0; r < 4; r++) acc[i][j][r] = 0.f;

    const int niter = K >> 4;

    loadA(0, 0); loadB(0, 0); cp_commit();

    for (int it = 0; it < niter; it++) {
        const int buf = it & 1;
        if (it + 1 < niter) {
            loadA(buf ^ 1, (it + 1) * BK);
            loadB(buf ^ 1, (it + 1) * BK);
            cp_commit();
            cp_wait<1>();
        } else {
            cp_wait<0>();
        }
        __syncthreads();

        const float* __restrict__ At = sA[buf];
        const float* __restrict__ Bt = sB[buf];
#pragma unroll
        for (int kk = 0; kk < BK; kk += 8) {
            uint32_t ua[4][4], ub[4][2];
#pragma unroll
            for (int mf = 0; mf < 4; mf++) {
                const int m = warp_m * 64 + mf * 16 + g;
                const int k = kk + t;
                if (AMODE == 0) {
                    ua[mf][0] = to_tf32(At[m * 20 + k]);
                    ua[mf][1] = to_tf32(At[(m + 8) * 20 + k]);
                    ua[mf][2] = to_tf32(At[m * 20 + k + 4]);
                    ua[mf][3] = to_tf32(At[(m + 8) * 20 + k + 4]);
                } else {
                    ua[mf][0] = to_tf32(At[k * 136 + m]);
                    ua[mf][1] = to_tf32(At[k * 136 + m + 8]);
                    ua[mf][2] = to_tf32(At[(k + 4) * 136 + m]);
                    ua[mf][3] = to_tf32(At[(k + 4) * 136 + m + 8]);
                }
            }
#pragma unroll
            for (int nf = 0; nf < 4; nf++) {
                const int n = warp_n * 32 + nf * 8 + g;
                const int k = kk + t;
                if (BMODE == 0) {
                    ub[nf][0] = to_tf32(Bt[n * 20 + k]);
                    ub[nf][1] = to_tf32(Bt[n * 20 + k + 4]);
                } else {
                    ub[nf][0] = to_tf32(Bt[k * 136 + n]);
                    ub[nf][1] = to_tf32(Bt[(k + 4) * 136 + n]);
                }
            }
#pragma unroll
            for (int mf = 0; mf < 4; mf++)
#pragma unroll
                for (int nf = 0; nf < 4; nf++) {
                    asm volatile(
                        "mma.sync.aligned.m16n8k8.row.col.f32.tf32.tf32.f32 "
                        "{%0,%1,%2,%3}, {%4,%5,%6,%7}, {%8,%9}, {%0,%1,%2,%3};"
                        : "+f"(acc[mf][nf][0]), "+f"(acc[mf][nf][1]),
                          "+f"(acc[mf][nf][2]), "+f"(acc[mf][nf][3])
                        : "r"(ua[mf][0]), "r"(ua[mf][1]), "r"(ua[mf][2]), "r"(ua[mf][3]),
                          "r"(ub[nf][0]), "r"(ub[nf][1]));
                }
        }
        __syncthreads();
    }

    // ---- epilogue: direct STG.64, fused alpha + bias ----
#pragma unroll
    for (int mf = 0; mf < 4; mf++) {
        const int row = m0 + warp_m * 64 + mf * 16 + g;
#pragma unroll
        for (int nf = 0; nf < 4; nf++) {
            const int col = n0 + warp_n * 32 + nf * 8 + t * 2;
            float b0 = 0.f, b1 = 0.f;
            if (bias) { b0 = bias[col]; b1 = bias[col + 1]; }
            float2 v0 = make_float2(acc[mf][nf][0] * alpha + b0,
                                    acc[mf][nf][1] * alpha + b1);
            float2 v1 = make_float2(acc[mf][nf][2] * alpha + b0,
                                    acc[mf][nf][3] * alpha + b1);
            *(float2*)&C[(long long)row * ldc + col] = v0;
            *(float2*)&C[(long long)(row + 8) * ldc + col] = v1;
        }
    }
}

// ---------------- combined softmax(e) + softmax(minmaxnorm(e,mask)) --------
__device__ __forceinline__ float warpMax(float v) {
#pragma unroll
    for (int o = 16; o > 0; o >>= 1) v = fmaxf(v, __shfl_xor_sync(0xffffffffu, v, o));
    return v;
}
__device__ __forceinline__ float warpMin(float v) {
#pragma unroll
    for (int o = 16; o > 0; o >>= 1) v = fminf(v, __shfl_xor_sync(0xffffffffu, v, o));
    return v;
}
__device__ __forceinline__ float warpSum(float v) {
#pragma unroll
    for (int o = 16; o > 0; o >>= 1) v += __shfl_xor_sync(0xffffffffu, v, o);
    return v;
}

__global__ __launch_bounds__(256) void attn_combine_kernel(
    float* __restrict__ E, const int* __restrict__ linkage)
{
    const int H = HIGH;
    const int l = blockIdx.x;
    const int b = blockIdx.y;
    float* row = E + ((long long)b * LOW + l) * H;
    const int* mrow = linkage + (long long)l * H;

    __shared__ float se[HIGH];
    __shared__ unsigned char smk[HIGH];
    __shared__ float bufg[8], bufn[8], bufx[8], bufs1[8], bufs2[8];

    const int tid = threadIdx.x;
    const int lane = tid & 31, wid = tid >> 5;
    const float BIGV = 9.0e15f;

    float gmax = -3.0e38f, mn = BIGV, mx = -BIGV;
    for (int h = tid; h < H; h += 256) {
        float v = row[h];
        int m = mrow[h];
        se[h] = v;
        smk[h] = (unsigned char)(m > 0);
        gmax = fmaxf(gmax, v);
        if (m > 0) { mn = fminf(mn, v); mx = fmaxf(mx, v); }
    }
    gmax = warpMax(gmax); mn = warpMin(mn); mx = warpMax(mx);
    if (lane == 0) { bufg[wid] = gmax; bufn[wid] = mn; bufx[wid] = mx; }
    __syncthreads();
    float GM = bufg[0], MN = bufn[0], MX = bufx[0];
#pragma unroll
    for (int i = 1; i < 8; i++) {
        GM = fmaxf(GM, bufg[i]); MN = fminf(MN, bufn[i]); MX = fmaxf(MX, bufx[i]);
    }

    float den = MX - MN;
    if (den == 0.f) den = 1e-6f;
    const float rden = 1.f / den;
    const float lmax = (MX - MN) * rden;

    float gsum = 0.f, lsum = 0.f;
    for (int h = tid; h < H; h += 256) {
        float v = se[h];
        gsum += __expf(v - GM);
        if (smk[h]) lsum += __expf((v - MN) * rden - lmax);
    }
    gsum = warpSum(gsum); lsum = warpSum(lsum);
    if (lane == 0) { bufs1[wid] = gsum; bufs2[wid] = lsum; }
    __syncthreads();
    float GS = 0.f, LS = 0.f;
#pragma unroll
    for (int i = 0; i < 8; i++) { GS += bufs1[i]; LS += bufs2[i]; }
    const float rg = 1.f / GS, rl = 1.f / LS;

    for (int h = tid; h < H; h += 256) {
        float v = se[h];
        float o = __expf(v - GM) * rg;
        if (smk[h]) o += __expf((v - MN) * rden - lmax) * rl;
        row[h] = o;
    }
}

// ---------------- launch ----------------------------------------------------
extern "C" void kernel_launch(void* const* d_in, const int* in_sizes, int n_in,
                              void* d_out, int out_size)
{
    const float* x    = (const float*)d_in[0];
    const int*   link = (const int*)  d_in[1];
    const float* wq_w = (const float*)d_in[2];
    const float* wq_b = (const float*)d_in[3];
    const float* wk_w = (const float*)d_in[4];
    const float* wk_b = (const float*)d_in[5];
    const float* wv_w = (const float*)d_in[6];
    const float* wv_b = (const float*)d_in[7];
    const float* o_w  = (const float*)d_in[8];
    const float* o_b  = (const float*)d_in[9];
    float* out = (float*)d_out;

    float *Q, *Km, *V, *E, *X;
    cudaGetSymbolAddress((void**)&Q,  g_Q);
    cudaGetSymbolAddress((void**)&Km, g_K);
    cudaGetSymbolAddress((void**)&V,  g_V);
    cudaGetSymbolAddress((void**)&E,  g_E);
    cudaGetSymbolAddress((void**)&X,  g_X);

    const int MT = BB * NTOK;
    dim3 blk(256);

    // Q = x @ wq_w^T + wq_b           [16384, 512]
    gemm_tc<0, 0><<<dim3(LOW / 128, MT / 128, 1), blk>>>(
        MT, LOW, LOW, x, LOW, 0, wq_w, LOW, 0, Q, LOW, 0, wq_b, 1.f);
    // K = x @ wk_w^T + wk_b           [16384, 4096]
    gemm_tc<0, 0><<<dim3(HIGH / 128, MT / 128, 1), blk>>>(
        MT, HIGH, LOW, x, LOW, 0, wk_w, LOW, 0, Km, HIGH, 0, wk_b, 1.f);
    // V = x @ wv_w^T + wv_b           [16384, 512]
    gemm_tc<0, 0><<<dim3(LOW / 128, MT / 128, 1), blk>>>(
        MT, LOW, LOW, x, LOW, 0, wv_w, LOW, 0, V, LOW, 0, wv_b, 1.f);

    // e[b] = Q[b]^T @ K[b] / sqrt(HIGH):  A = Q [K=NTOK, M=LOW] (dim-contig),
    //                                     B = K [K=NTOK, N=HIGH] (dim-contig)
    gemm_tc<1, 1><<<dim3(HIGH / 128, LOW / 128, BB), blk>>>(
        LOW, HIGH, NTOK,
        Q, LOW, (long long)NTOK * LOW,
        Km, HIGH, (long long)NTOK * HIGH,
        E, HIGH, (long long)LOW * HIGH,
        nullptr, 0.015625f);

    // E <- softmax_global(E) + softmax_local(minmaxnorm(E, mask))  (in place)
    attn_combine_kernel<<<dim3(LOW, BB), 256>>>(E, link);

    // x[b] = V[b] @ E[b]:  A = V [NTOK, LOW] k-contig, B = E [K=LOW, N=HIGH] dim-contig
    gemm_tc<0, 1><<<dim3(HIGH / 128, NTOK / 128, BB), blk>>>(
        NTOK, HIGH, LOW,
        V, LOW, (long long)NTOK * LOW,
        E, HIGH, (long long)LOW * HIGH,
        X, HIGH, (long long)NTOK * HIGH,
        nullptr, 1.f);

    // out = x @ o_w^T + o_b           [16384, 4096]
    gemm_tc<0, 0><<<dim3(HIGH / 128, MT / 128, 1), blk>>>(
        MT, HIGH, HIGH, X, HIGH, 0, o_w, HIGH, 0, out, HIGH, 0, o_b, 1.f);
}

// round 4
// speedup vs baseline: 3.4291x; 1.0730x over previous
#include <cuda_runtime.h>
#include <cstdint>

#define BB    8
#define NTOK  2048
#define LOW   512
#define HIGH  4096

// ---------------- scratch (static device memory; no allocs allowed) -------
__device__ float g_Q[(size_t)BB * NTOK * LOW];
__device__ float g_K[(size_t)BB * NTOK * HIGH];
__device__ float g_V[(size_t)BB * NTOK * LOW];
__device__ float g_E[(size_t)BB * LOW * HIGH];
__device__ float g_X[(size_t)BB * NTOK * HIGH];
// tf32-rounded copies of external inputs
__device__ float g_XR[(size_t)BB * NTOK * LOW];
__device__ float g_WQ[(size_t)LOW * LOW];
__device__ float g_WK[(size_t)HIGH * LOW];
__device__ float g_WV[(size_t)LOW * LOW];
__device__ float g_OW[(size_t)HIGH * HIGH];

// ---------------- helpers ---------------------------------------------------
__device__ __forceinline__ uint32_t smem_u32(const void* p) {
    return (uint32_t)__cvta_generic_to_shared(p);
}
__device__ __forceinline__ void cp16(uint32_t s, const void* g) {
    asm volatile("cp.async.cg.shared.global [%0], [%1], 16;" :: "r"(s), "l"(g));
}
__device__ __forceinline__ void cp_commit() {
    asm volatile("cp.async.commit_group;" ::: "memory");
}
template <int N>
__device__ __forceinline__ void cp_wait() {
    asm volatile("cp.async.wait_group %0;" :: "n"(N) : "memory");
}
__device__ __forceinline__ float tf32r(float f) {
    uint32_t r;
    asm("cvt.rna.tf32.f32 %0, %1;" : "=r"(r) : "f"(f));
    return __uint_as_float(r);
}

// ---------------- tf32 rounding pass ----------------------------------------
__global__ __launch_bounds__(256) void round_tf32_kernel(
    float* __restrict__ d, const float* __restrict__ s, int n4)
{
    int i = blockIdx.x * 256 + threadIdx.x;
    if (i < n4) {
        float4 v = ((const float4*)s)[i];
        v.x = tf32r(v.x); v.y = tf32r(v.y); v.z = tf32r(v.z); v.w = tf32r(v.w);
        ((float4*)d)[i] = v;
    }
}

// ---------------- tf32 tensor-core GEMM -------------------------------------
// C[m,n] = alpha * sum_k A(m,k) * B(n,k) + bias[n]    (inputs pre-rounded tf32)
// MODE 0: operand stored [dim, K] (k contiguous)  -> smem [dim][BK], stride 36
// MODE 1: operand stored [K, dim] (dim contiguous)-> smem [k][dim], stride 132
#define Bb      128
#define BK      32
#define STAGES  3

template <int AMODE, int BMODE>
__global__ __launch_bounds__(256, 2) void gemm_tc(
    int M, int N, int K,
    const float* __restrict__ A, int lda, long long strideA,
    const float* __restrict__ B, int ldb, long long strideB,
    float* __restrict__ C, int ldc, long long strideC,
    const float* __restrict__ bias, float alpha, int round_out)
{
    constexpr int ATF = AMODE ? (BK * 132) : (Bb * 36);
    constexpr int BTF = BMODE ? (BK * 132) : (Bb * 36);

    extern __shared__ float sm[];
    float* sAst = sm;                       // [STAGES][ATF]
    float* sBst = sm + STAGES * ATF;        // [STAGES][BTF]

    const int tid = threadIdx.x;
    const int wid = tid >> 5;
    const int lane = tid & 31;
    const int g = lane >> 2;      // 0..7
    const int t = lane & 3;       // 0..3
    const int warp_m = wid & 1;   // 2 warps over M
    const int warp_n = wid >> 1;  // 4 warps over N

    A += (long long)blockIdx.z * strideA;
    B += (long long)blockIdx.z * strideB;
    C += (long long)blockIdx.z * strideC;
    const int m0 = blockIdx.y * Bb;
    const int n0 = blockIdx.x * Bb;

    auto loadA = [&](int st, int k0) {
        uint32_t s0 = smem_u32(sAst + st * ATF);
#pragma unroll
        for (int r = 0; r < 4; r++) {
            int i = tid + r * 256;
            if (AMODE == 0) {
                int row = i >> 3, kq = i & 7;
                cp16(s0 + (uint32_t)(row * 144 + kq * 16),
                     &A[(long long)(m0 + row) * lda + k0 + kq * 4]);
            } else {
                int k = i >> 5, dq = i & 31;
                cp16(s0 + (uint32_t)(k * 528 + dq * 16),
                     &A[(long long)(k0 + k) * lda + m0 + dq * 4]);
            }
        }
    };
    auto loadB = [&](int st, int k0) {
        uint32_t s0 = smem_u32(sBst + st * BTF);
#pragma unroll
        for (int r = 0; r < 4; r++) {
            int i = tid + r * 256;
            if (BMODE == 0) {
                int row = i >> 3, kq = i & 7;
                cp16(s0 + (uint32_t)(row * 144 + kq * 16),
                     &B[(long long)(n0 + row) * ldb + k0 + kq * 4]);
            } else {
                int k = i >> 5, dq = i & 31;
                cp16(s0 + (uint32_t)(k * 528 + dq * 16),
                     &B[(long long)(k0 + k) * ldb + n0 + dq * 4]);
            }
        }
    };

    float acc[4][4][4];
#pragma unroll
    for (int i = 0; i < 4; i++)
#pragma unroll
        for (int j = 0; j < 4; j++)
#pragma unroll
            for (int r = 0; r < 4; r++) acc[i][j][r] = 0.f;

    const int niter = K >> 5;

    // prologue: stages 0..STAGES-2
#pragma unroll
    for (int s = 0; s < STAGES - 1; s++) {
        loadA(s, s * BK);
        loadB(s, s * BK);
        cp_commit();
    }

    for (int it = 0; it < niter; it++) {
        cp_wait<STAGES - 2>();
        __syncthreads();

        {   // prefetch stage it+STAGES-1 into ring slot (frees slot computed at it-1)
            int ns = it + STAGES - 1;
            if (ns < niter) {
                int st = ns % STAGES;
                loadA(st, ns * BK);
                loadB(st, ns * BK);
            }
            cp_commit();
        }

        const uint32_t* __restrict__ At =
            (const uint32_t*)(sAst + (it % STAGES) * ATF);
        const uint32_t* __restrict__ Bt =
            (const uint32_t*)(sBst + (it % STAGES) * BTF);

#pragma unroll
        for (int kk = 0; kk < BK; kk += 8) {
            uint32_t ua[4][4], ub[4][2];
            const int k = kk + t;
#pragma unroll
            for (int mf = 0; mf < 4; mf++) {
                const int m = warp_m * 64 + mf * 16 + g;
                if (AMODE == 0) {
                    ua[mf][0] = At[m * 36 + k];
                    ua[mf][1] = At[(m + 8) * 36 + k];
                    ua[mf][2] = At[m * 36 + k + 4];
                    ua[mf][3] = At[(m + 8) * 36 + k + 4];
                } else {
                    ua[mf][0] = At[k * 132 + m];
                    ua[mf][1] = At[k * 132 + m + 8];
                    ua[mf][2] = At[(k + 4) * 132 + m];
                    ua[mf][3] = At[(k + 4) * 132 + m + 8];
                }
            }
#pragma unroll
            for (int nf = 0; nf < 4; nf++) {
                const int n = warp_n * 32 + nf * 8 + g;
                if (BMODE == 0) {
                    ub[nf][0] = Bt[n * 36 + k];
                    ub[nf][1] = Bt[n * 36 + k + 4];
                } else {
                    ub[nf][0] = Bt[k * 132 + n];
                    ub[nf][1] = Bt[(k + 4) * 132 + n];
                }
            }
#pragma unroll
            for (int mf = 0; mf < 4; mf++)
#pragma unroll
                for (int nf = 0; nf < 4; nf++) {
                    asm volatile(
                        "mma.sync.aligned.m16n8k8.row.col.f32.tf32.tf32.f32 "
                        "{%0,%1,%2,%3}, {%4,%5,%6,%7}, {%8,%9}, {%0,%1,%2,%3};"
                        : "+f"(acc[mf][nf][0]), "+f"(acc[mf][nf][1]),
                          "+f"(acc[mf][nf][2]), "+f"(acc[mf][nf][3])
                        : "r"(ua[mf][0]), "r"(ua[mf][1]), "r"(ua[mf][2]), "r"(ua[mf][3]),
                          "r"(ub[nf][0]), "r"(ub[nf][1]));
                }
        }
    }

    // ---- epilogue: direct STG.64, fused alpha + bias (+ optional tf32 round)
#pragma unroll
    for (int mf = 0; mf < 4; mf++) {
        const int row = m0 + warp_m * 64 + mf * 16 + g;
#pragma unroll
        for (int nf = 0; nf < 4; nf++) {
            const int col = n0 + warp_n * 32 + nf * 8 + t * 2;
            float b0 = 0.f, b1 = 0.f;
            if (bias) { b0 = bias[col]; b1 = bias[col + 1]; }
            float v00 = acc[mf][nf][0] * alpha + b0;
            float v01 = acc[mf][nf][1] * alpha + b1;
            float v10 = acc[mf][nf][2] * alpha + b0;
            float v11 = acc[mf][nf][3] * alpha + b1;
            if (round_out) {
                v00 = tf32r(v00); v01 = tf32r(v01);
                v10 = tf32r(v10); v11 = tf32r(v11);
            }
            *(float2*)&C[(long long)row * ldc + col] = make_float2(v00, v01);
            *(float2*)&C[(long long)(row + 8) * ldc + col] = make_float2(v10, v11);
        }
    }
}

// ---------------- combined softmax(e) + softmax(minmaxnorm(e,mask)) --------
__device__ __forceinline__ float warpMax(float v) {
#pragma unroll
    for (int o = 16; o > 0; o >>= 1) v = fmaxf(v, __shfl_xor_sync(0xffffffffu, v, o));
    return v;
}
__device__ __forceinline__ float warpMin(float v) {
#pragma unroll
    for (int o = 16; o > 0; o >>= 1) v = fminf(v, __shfl_xor_sync(0xffffffffu, v, o));
    return v;
}
__device__ __forceinline__ float warpSum(float v) {
#pragma unroll
    for (int o = 16; o > 0; o >>= 1) v += __shfl_xor_sync(0xffffffffu, v, o);
    return v;
}

__global__ __launch_bounds__(256) void attn_combine_kernel(
    float* __restrict__ E, const int* __restrict__ linkage)
{
    const int H = HIGH;
    const int l = blockIdx.x;
    const int b = blockIdx.y;
    float* row = E + ((long long)b * LOW + l) * H;
    const int* mrow = linkage + (long long)l * H;

    __shared__ float se[HIGH];
    __shared__ unsigned char smk[HIGH];
    __shared__ float bufg[8], bufn[8], bufx[8], bufs1[8], bufs2[8];

    const int tid = threadIdx.x;
    const int lane = tid & 31, wid = tid >> 5;
    const float BIGV = 9.0e15f;

    float gmax = -3.0e38f, mn = BIGV, mx = -BIGV;
    for (int h = tid; h < H; h += 256) {
        float v = row[h];
        int m = mrow[h];
        se[h] = v;
        smk[h] = (unsigned char)(m > 0);
        gmax = fmaxf(gmax, v);
        if (m > 0) { mn = fminf(mn, v); mx = fmaxf(mx, v); }
    }
    gmax = warpMax(gmax); mn = warpMin(mn); mx = warpMax(mx);
    if (lane == 0) { bufg[wid] = gmax; bufn[wid] = mn; bufx[wid] = mx; }
    __syncthreads();
    float GM = bufg[0], MN = bufn[0], MX = bufx[0];
#pragma unroll
    for (int i = 1; i < 8; i++) {
        GM = fmaxf(GM, bufg[i]); MN = fminf(MN, bufn[i]); MX = fmaxf(MX, bufx[i]);
    }

    float den = MX - MN;
    if (den == 0.f) den = 1e-6f;
    const float rden = 1.f / den;
    const float lmax = (MX - MN) * rden;

    float gsum = 0.f, lsum = 0.f;
    for (int h = tid; h < H; h += 256) {
        float v = se[h];
        gsum += __expf(v - GM);
        if (smk[h]) lsum += __expf((v - MN) * rden - lmax);
    }
    gsum = warpSum(gsum); lsum = warpSum(lsum);
    if (lane == 0) { bufs1[wid] = gsum; bufs2[wid] = lsum; }
    __syncthreads();
    float GS = 0.f, LS = 0.f;
#pragma unroll
    for (int i = 0; i < 8; i++) { GS += bufs1[i]; LS += bufs2[i]; }
    const float rg = 1.f / GS, rl = 1.f / LS;

    for (int h = tid; h < H; h += 256) {
        float v = se[h];
        float o = __expf(v - GM) * rg;
        if (smk[h]) o += __expf((v - MN) * rden - lmax) * rl;
        row[h] = tf32r(o);   // next consumer is a tf32 GEMM
    }
}

// ---------------- launch ----------------------------------------------------
extern "C" void kernel_launch(void* const* d_in, const int* in_sizes, int n_in,
                              void* d_out, int out_size)
{
    const float* x    = (const float*)d_in[0];
    const int*   link = (const int*)  d_in[1];
    const float* wq_w = (const float*)d_in[2];
    const float* wq_b = (const float*)d_in[3];
    const float* wk_w = (const float*)d_in[4];
    const float* wk_b = (const float*)d_in[5];
    const float* wv_w = (const float*)d_in[6];
    const float* wv_b = (const float*)d_in[7];
    const float* o_w  = (const float*)d_in[8];
    const float* o_b  = (const float*)d_in[9];
    float* out = (float*)d_out;

    float *Q, *Km, *V, *E, *X, *XR, *WQ, *WK, *WV, *OW;
    cudaGetSymbolAddress((void**)&Q,  g_Q);
    cudaGetSymbolAddress((void**)&Km, g_K);
    cudaGetSymbolAddress((void**)&V,  g_V);
    cudaGetSymbolAddress((void**)&E,  g_E);
    cudaGetSymbolAddress((void**)&X,  g_X);
    cudaGetSymbolAddress((void**)&XR, g_XR);
    cudaGetSymbolAddress((void**)&WQ, g_WQ);
    cudaGetSymbolAddress((void**)&WK, g_WK);
    cudaGetSymbolAddress((void**)&WV, g_WV);
    cudaGetSymbolAddress((void**)&OW, g_OW);

    constexpr int SM00 = STAGES * 2 * (Bb * 36) * 4;               // 110592
    constexpr int SM11 = STAGES * 2 * (BK * 132) * 4;              // 101376
    constexpr int SM01 = STAGES * ((Bb * 36) + (BK * 132)) * 4;    // 105984
    cudaFuncSetAttribute(gemm_tc<0, 0>, cudaFuncAttributeMaxDynamicSharedMemorySize, SM00);
    cudaFuncSetAttribute(gemm_tc<1, 1>, cudaFuncAttributeMaxDynamicSharedMemorySize, SM11);
    cudaFuncSetAttribute(gemm_tc<0, 1>, cudaFuncAttributeMaxDynamicSharedMemorySize, SM01);

    const int MT = BB * NTOK;
    dim3 blk(256);

    // --- pre-round external inputs to tf32 (one-time elementwise pass) ---
    auto launch_round = [&](float* d, const float* s, long long n) {
        int n4 = (int)(n >> 2);
        round_tf32_kernel<<<(n4 + 255) / 256, 256>>>(d, s, n4);
    };
    launch_round(XR, x,    (long long)MT * LOW);
    launch_round(WQ, wq_w, (long long)LOW * LOW);
    launch_round(WK, wk_w, (long long)HIGH * LOW);
    launch_round(WV, wv_w, (long long)LOW * LOW);
    launch_round(OW, o_w,  (long long)HIGH * HIGH);

    // Q = x @ wq_w^T + wq_b           [16384, 512]   (round for e-GEMM)
    gemm_tc<0, 0><<<dim3(LOW / 128, MT / 128, 1), blk, SM00>>>(
        MT, LOW, LOW, XR, LOW, 0, WQ, LOW, 0, Q, LOW, 0, wq_b, 1.f, 1);
    // K = x @ wk_w^T + wk_b           [16384, 4096]
    gemm_tc<0, 0><<<dim3(HIGH / 128, MT / 128, 1), blk, SM00>>>(
        MT, HIGH, LOW, XR, LOW, 0, WK, LOW, 0, Km, HIGH, 0, wk_b, 1.f, 1);
    // V = x @ wv_w^T + wv_b           [16384, 512]
    gemm_tc<0, 0><<<dim3(LOW / 128, MT / 128, 1), blk, SM00>>>(
        MT, LOW, LOW, XR, LOW, 0, WV, LOW, 0, V, LOW, 0, wv_b, 1.f, 1);

    // e[b] = Q[b]^T @ K[b] / sqrt(HIGH)   (scores stay fp32 for softmax)
    gemm_tc<1, 1><<<dim3(HIGH / 128, LOW / 128, BB), blk, SM11>>>(
        LOW, HIGH, NTOK,
        Q, LOW, (long long)NTOK * LOW,
        Km, HIGH, (long long)NTOK * HIGH,
        E, HIGH, (long long)LOW * HIGH,
        nullptr, 0.015625f, 0);

    // E <- softmax_global(E) + softmax_local(minmaxnorm(E, mask))  (tf32-rounded)
    attn_combine_kernel<<<dim3(LOW, BB), 256>>>(E, link);

    // x[b] = V[b] @ E[b]   (round X for the final GEMM)
    gemm_tc<0, 1><<<dim3(HIGH / 128, NTOK / 128, BB), blk, SM01>>>(
        NTOK, HIGH, LOW,
        V, LOW, (long long)NTOK * LOW,
        E, HIGH, (long long)LOW * HIGH,
        X, HIGH, (long long)NTOK * HIGH,
        nullptr, 1.f, 1);

    // out = x @ o_w^T + o_b           [16384, 4096]  (full fp32 output)
    gemm_tc<0, 0><<<dim3(HIGH / 128, MT / 128, 1), blk, SM00>>>(
        MT, HIGH, HIGH, X, HIGH, 0, OW, HIGH, 0, out, HIGH, 0, o_b, 1.f, 0);
}

// round 5
// speedup vs baseline: 3.8969x; 1.1364x over previous
#include <cuda_runtime.h>
#include <cstdint>

#define BB    8
#define NTOK  2048
#define LOW   512
#define HIGH  4096

// ---------------- scratch (static device memory; no allocs allowed) -------
__device__ float g_Q[(size_t)BB * LOW * NTOK];    // QT  [b][l][n]
__device__ float g_K[(size_t)BB * HIGH * NTOK];   // KT  [b][h][n]
__device__ float g_V[(size_t)BB * NTOK * LOW];    // V   [b][n][l]
__device__ float g_E[(size_t)BB * LOW * HIGH];    // e -> combined attn
__device__ float g_X[(size_t)BB * NTOK * HIGH];   // V @ attn
// tf32-rounded copies of external inputs
__device__ float g_XR[(size_t)BB * NTOK * LOW];
__device__ float g_WQ[(size_t)LOW * LOW];
__device__ float g_WK[(size_t)HIGH * LOW];
__device__ float g_WV[(size_t)LOW * LOW];
__device__ float g_OW[(size_t)HIGH * HIGH];

// ---------------- helpers ---------------------------------------------------
__device__ __forceinline__ uint32_t smem_u32(const void* p) {
    return (uint32_t)__cvta_generic_to_shared(p);
}
__device__ __forceinline__ void cp16(uint32_t s, const void* g) {
    asm volatile("cp.async.cg.shared.global [%0], [%1], 16;" :: "r"(s), "l"(g));
}
__device__ __forceinline__ void cp_commit() {
    asm volatile("cp.async.commit_group;" ::: "memory");
}
template <int N>
__device__ __forceinline__ void cp_wait() {
    asm volatile("cp.async.wait_group %0;" :: "n"(N) : "memory");
}
__device__ __forceinline__ float tf32r(float f) {
    uint32_t r;
    asm("cvt.rna.tf32.f32 %0, %1;" : "=r"(r) : "f"(f));
    return __uint_as_float(r);
}
__device__ __forceinline__ void ldsm4(uint32_t& d0, uint32_t& d1,
                                      uint32_t& d2, uint32_t& d3, uint32_t a) {
    asm volatile("ldmatrix.sync.aligned.m8n8.x4.shared.b16 {%0,%1,%2,%3}, [%4];"
                 : "=r"(d0), "=r"(d1), "=r"(d2), "=r"(d3) : "r"(a));
}

// ---------------- tf32 rounding pass ----------------------------------------
__global__ __launch_bounds__(256) void round_tf32_kernel(
    float* __restrict__ d, const float* __restrict__ s, int n4)
{
    int i = blockIdx.x * 256 + threadIdx.x;
    if (i < n4) {
        float4 v = ((const float4*)s)[i];
        v.x = tf32r(v.x); v.y = tf32r(v.y); v.z = tf32r(v.z); v.w = tf32r(v.w);
        ((float4*)d)[i] = v;
    }
}

// ---------------- tf32 tensor-core GEMM -------------------------------------
// C[m,n] = alpha * sum_k A(m,k) * B(n,k) + bias
// A is always stored [M, K] (k contiguous) -> smem [m][k] stride 36, ldmatrix.
// BMODE 0: B stored [N, K] (k contig)  -> smem [n][k] stride 36, ldmatrix.
// BMODE 1: B stored [K, N] (n contig)  -> smem [k][n] stride 132, scalar LDS.
// BIASROW 1: bias indexed by m (row), else by n (col).
#define Bb      128
#define BK      32
#define STAGES  3

template <int BMODE, int BIASROW>
__global__ __launch_bounds__(256, 2) void gemm_tc(
    int M, int N, int K,
    const float* __restrict__ A, int lda, long long strideA,
    const float* __restrict__ B, int ldb, long long strideB,
    float* __restrict__ C, int ldc, long long strideC,
    const float* __restrict__ bias, float alpha, int round_out)
{
    constexpr int ATF = Bb * 36;
    constexpr int BTF = BMODE ? (BK * 132) : (Bb * 36);

    extern __shared__ float sm[];
    float* sAst = sm;                       // [STAGES][ATF]
    float* sBst = sm + STAGES * ATF;        // [STAGES][BTF]

    const int tid = threadIdx.x;
    const int wid = tid >> 5;
    const int lane = tid & 31;
    const int g = lane >> 2;      // 0..7
    const int t = lane & 3;       // 0..3
    const int warp_m = wid & 1;   // 2 warps over M
    const int warp_n = wid >> 1;  // 4 warps over N
    const int lmat = lane >> 3;   // ldmatrix: which 8x8 matrix
    const int lrow = lane & 7;    // ldmatrix: row within matrix

    A += (long long)blockIdx.z * strideA;
    B += (long long)blockIdx.z * strideB;
    C += (long long)blockIdx.z * strideC;
    const int m0 = blockIdx.y * Bb;
    const int n0 = blockIdx.x * Bb;

    auto loadA = [&](int st, int k0) {
        uint32_t s0 = smem_u32(sAst + st * ATF);
#pragma unroll
        for (int r = 0; r < 4; r++) {
            int i = tid + r * 256;
            int row = i >> 3, kq = i & 7;
            cp16(s0 + (uint32_t)(row * 144 + kq * 16),
                 &A[(long long)(m0 + row) * lda + k0 + kq * 4]);
        }
    };
    auto loadB = [&](int st, int k0) {
        uint32_t s0 = smem_u32(sBst + st * BTF);
#pragma unroll
        for (int r = 0; r < 4; r++) {
            int i = tid + r * 256;
            if (BMODE == 0) {
                int row = i >> 3, kq = i & 7;
                cp16(s0 + (uint32_t)(row * 144 + kq * 16),
                     &B[(long long)(n0 + row) * ldb + k0 + kq * 4]);
            } else {
                int k = i >> 5, dq = i & 31;
                cp16(s0 + (uint32_t)(k * 528 + dq * 16),
                     &B[(long long)(k0 + k) * ldb + n0 + dq * 4]);
            }
        }
    };

    // Per-thread ldmatrix row offsets (floats), constant across iters/kk.
    // A fragment mf: matrices {m-lo,k-lo}, {m-hi,k-lo}, {m-lo,k-hi}, {m-hi,k-hi}
    int a_off[4];
#pragma unroll
    for (int mf = 0; mf < 4; mf++)
        a_off[mf] = (warp_m * 64 + mf * 16 + ((lmat & 1) << 3) + lrow) * 36
                    + ((lmat >> 1) << 2);
    // B fragment pair nf2: matrices {n-lo,k-lo}, {n-lo,k-hi}, {n-hi,k-lo}, {n-hi,k-hi}
    int b_off[2];
#pragma unroll
    for (int nf2 = 0; nf2 < 2; nf2++)
        b_off[nf2] = (warp_n * 32 + nf2 * 16 + ((lmat >> 1) << 3) + lrow) * 36
                     + ((lmat & 1) << 2);

    float acc[4][4][4];
#pragma unroll
    for (int i = 0; i < 4; i++)
#pragma unroll
        for (int j = 0; j < 4; j++)
#pragma unroll
            for (int r = 0; r < 4; r++) acc[i][j][r] = 0.f;

    const int niter = K >> 5;

#pragma unroll
    for (int s = 0; s < STAGES - 1; s++) {
        loadA(s, s * BK);
        loadB(s, s * BK);
        cp_commit();
    }

    for (int it = 0; it < niter; it++) {
        cp_wait<STAGES - 2>();
        __syncthreads();

        {
            int ns = it + STAGES - 1;
            if (ns < niter) {
                int st = ns % STAGES;
                loadA(st, ns * BK);
                loadB(st, ns * BK);
            }
            cp_commit();
        }

        const int stg = it % STAGES;
        const uint32_t sa = smem_u32(sAst + stg * ATF);
        const uint32_t sb = smem_u32(sBst + stg * BTF);
        const uint32_t* __restrict__ Bt = (const uint32_t*)(sBst + stg * BTF);

#pragma unroll
        for (int kk = 0; kk < BK; kk += 8) {
            uint32_t ua[4][4], ub[4][2];
#pragma unroll
            for (int mf = 0; mf < 4; mf++)
                ldsm4(ua[mf][0], ua[mf][1], ua[mf][2], ua[mf][3],
                      sa + (uint32_t)(a_off[mf] + kk) * 4u);
            if (BMODE == 0) {
#pragma unroll
                for (int nf2 = 0; nf2 < 2; nf2++)
                    ldsm4(ub[nf2 * 2][0], ub[nf2 * 2][1],
                          ub[nf2 * 2 + 1][0], ub[nf2 * 2 + 1][1],
                          sb + (uint32_t)(b_off[nf2] + kk) * 4u);
            } else {
                const int k = kk + t;
#pragma unroll
                for (int nf = 0; nf < 4; nf++) {
                    const int n = warp_n * 32 + nf * 8 + g;
                    ub[nf][0] = Bt[k * 132 + n];
                    ub[nf][1] = Bt[(k + 4) * 132 + n];
                }
            }
#pragma unroll
            for (int mf = 0; mf < 4; mf++)
#pragma unroll
                for (int nf = 0; nf < 4; nf++) {
                    asm volatile(
                        "mma.sync.aligned.m16n8k8.row.col.f32.tf32.tf32.f32 "
                        "{%0,%1,%2,%3}, {%4,%5,%6,%7}, {%8,%9}, {%0,%1,%2,%3};"
                        : "+f"(acc[mf][nf][0]), "+f"(acc[mf][nf][1]),
                          "+f"(acc[mf][nf][2]), "+f"(acc[mf][nf][3])
                        : "r"(ua[mf][0]), "r"(ua[mf][1]), "r"(ua[mf][2]), "r"(ua[mf][3]),
                          "r"(ub[nf][0]), "r"(ub[nf][1]));
                }
        }
    }

    // ---- epilogue ----
#pragma unroll
    for (int mf = 0; mf < 4; mf++) {
        const int row = m0 + warp_m * 64 + mf * 16 + g;
        float br0 = 0.f, br1 = 0.f;
        if (BIASROW) { br0 = bias[row]; br1 = bias[row + 8]; }
#pragma unroll
        for (int nf = 0; nf < 4; nf++) {
            const int col = n0 + warp_n * 32 + nf * 8 + t * 2;
            float b0 = br0, b1 = br0, c0 = br1, c1 = br1;
            if (!BIASROW && bias) {
                b0 = bias[col]; b1 = bias[col + 1]; c0 = b0; c1 = b1;
            } else if (!BIASROW) {
                b0 = b1 = c0 = c1 = 0.f;
            }
            float v00 = acc[mf][nf][0] * alpha + b0;
            float v01 = acc[mf][nf][1] * alpha + b1;
            float v10 = acc[mf][nf][2] * alpha + c0;
            float v11 = acc[mf][nf][3] * alpha + c1;
            if (round_out) {
                v00 = tf32r(v00); v01 = tf32r(v01);
                v10 = tf32r(v10); v11 = tf32r(v11);
            }
            *(float2*)&C[(long long)row * ldc + col] = make_float2(v00, v01);
            *(float2*)&C[(long long)(row + 8) * ldc + col] = make_float2(v10, v11);
        }
    }
}

// ---------------- combined softmax(e) + softmax(minmaxnorm(e,mask)) --------
__device__ __forceinline__ float warpMax(float v) {
#pragma unroll
    for (int o = 16; o > 0; o >>= 1) v = fmaxf(v, __shfl_xor_sync(0xffffffffu, v, o));
    return v;
}
__device__ __forceinline__ float warpMin(float v) {
#pragma unroll
    for (int o = 16; o > 0; o >>= 1) v = fminf(v, __shfl_xor_sync(0xffffffffu, v, o));
    return v;
}
__device__ __forceinline__ float warpSum(float v) {
#pragma unroll
    for (int o = 16; o > 0; o >>= 1) v += __shfl_xor_sync(0xffffffffu, v, o);
    return v;
}

__global__ __launch_bounds__(256) void attn_combine_kernel(
    float* __restrict__ E, const int* __restrict__ linkage)
{
    const int H = HIGH;
    const int l = blockIdx.x;
    const int b = blockIdx.y;
    float* row = E + ((long long)b * LOW + l) * H;
    const int* mrow = linkage + (long long)l * H;

    __shared__ float se[HIGH];
    __shared__ unsigned char smk[HIGH];
    __shared__ float bufg[8], bufn[8], bufx[8], bufs1[8], bufs2[8];

    const int tid = threadIdx.x;
    const int lane = tid & 31, wid = tid >> 5;
    const float BIGV = 9.0e15f;

    float gmax = -3.0e38f, mn = BIGV, mx = -BIGV;
    for (int h = tid; h < H; h += 256) {
        float v = row[h];
        int m = mrow[h];
        se[h] = v;
        smk[h] = (unsigned char)(m > 0);
        gmax = fmaxf(gmax, v);
        if (m > 0) { mn = fminf(mn, v); mx = fmaxf(mx, v); }
    }
    gmax = warpMax(gmax); mn = warpMin(mn); mx = warpMax(mx);
    if (lane == 0) { bufg[wid] = gmax; bufn[wid] = mn; bufx[wid] = mx; }
    __syncthreads();
    float GM = bufg[0], MN = bufn[0], MX = bufx[0];
#pragma unroll
    for (int i = 1; i < 8; i++) {
        GM = fmaxf(GM, bufg[i]); MN = fminf(MN, bufn[i]); MX = fmaxf(MX, bufx[i]);
    }

    float den = MX - MN;
    if (den == 0.f) den = 1e-6f;
    const float rden = 1.f / den;
    const float lmax = (MX - MN) * rden;

    float gsum = 0.f, lsum = 0.f;
    for (int h = tid; h < H; h += 256) {
        float v = se[h];
        gsum += __expf(v - GM);
        if (smk[h]) lsum += __expf((v - MN) * rden - lmax);
    }
    gsum = warpSum(gsum); lsum = warpSum(lsum);
    if (lane == 0) { bufs1[wid] = gsum; bufs2[wid] = lsum; }
    __syncthreads();
    float GS = 0.f, LS = 0.f;
#pragma unroll
    for (int i = 0; i < 8; i++) { GS += bufs1[i]; LS += bufs2[i]; }
    const float rg = 1.f / GS, rl = 1.f / LS;

    for (int h = tid; h < H; h += 256) {
        float v = se[h];
        float o = __expf(v - GM) * rg;
        if (smk[h]) o += __expf((v - MN) * rden - lmax) * rl;
        row[h] = tf32r(o);   // next consumer is a tf32 GEMM
    }
}

// ---------------- launch ----------------------------------------------------
extern "C" void kernel_launch(void* const* d_in, const int* in_sizes, int n_in,
                              void* d_out, int out_size)
{
    const float* x    = (const float*)d_in[0];
    const int*   link = (const int*)  d_in[1];
    const float* wq_w = (const float*)d_in[2];
    const float* wq_b = (const float*)d_in[3];
    const float* wk_w = (const float*)d_in[4];
    const float* wk_b = (const float*)d_in[5];
    const float* wv_w = (const float*)d_in[6];
    const float* wv_b = (const float*)d_in[7];
    const float* o_w  = (const float*)d_in[8];
    const float* o_b  = (const float*)d_in[9];
    float* out = (float*)d_out;

    float *QT, *KT, *V, *E, *X, *XR, *WQ, *WK, *WV, *OW;
    cudaGetSymbolAddress((void**)&QT, g_Q);
    cudaGetSymbolAddress((void**)&KT, g_K);
    cudaGetSymbolAddress((void**)&V,  g_V);
    cudaGetSymbolAddress((void**)&E,  g_E);
    cudaGetSymbolAddress((void**)&X,  g_X);
    cudaGetSymbolAddress((void**)&XR, g_XR);
    cudaGetSymbolAddress((void**)&WQ, g_WQ);
    cudaGetSymbolAddress((void**)&WK, g_WK);
    cudaGetSymbolAddress((void**)&WV, g_WV);
    cudaGetSymbolAddress((void**)&OW, g_OW);

    constexpr int SM0 = STAGES * 2 * (Bb * 36) * 4;                    // 110592
    constexpr int SM1 = STAGES * ((Bb * 36) + (BK * 132)) * 4;         // 105984
    cudaFuncSetAttribute(gemm_tc<0, 0>, cudaFuncAttributeMaxDynamicSharedMemorySize, SM0);
    cudaFuncSetAttribute(gemm_tc<0, 1>, cudaFuncAttributeMaxDynamicSharedMemorySize, SM0);
    cudaFuncSetAttribute(gemm_tc<1, 0>, cudaFuncAttributeMaxDynamicSharedMemorySize, SM1);

    const int MT = BB * NTOK;
    dim3 blk(256);

    // --- pre-round external inputs to tf32 ---
    auto launch_round = [&](float* d, const float* s, long long n) {
        int n4 = (int)(n >> 2);
        round_tf32_kernel<<<(n4 + 255) / 256, 256>>>(d, s, n4);
    };
    launch_round(XR, x,    (long long)MT * LOW);
    launch_round(WQ, wq_w, (long long)LOW * LOW);
    launch_round(WK, wk_w, (long long)HIGH * LOW);
    launch_round(WV, wv_w, (long long)LOW * LOW);
    launch_round(OW, o_w,  (long long)HIGH * HIGH);

    // QT[b] = wq @ x[b]^T + wq_b (row bias)     [8][512][2048]
    gemm_tc<0, 1><<<dim3(NTOK / 128, LOW / 128, BB), blk, SM0>>>(
        LOW, NTOK, LOW,
        WQ, LOW, 0,
        XR, LOW, (long long)NTOK * LOW,
        QT, NTOK, (long long)LOW * NTOK,
        wq_b, 1.f, 1);
    // KT[b] = wk @ x[b]^T + wk_b (row bias)     [8][4096][2048]
    gemm_tc<0, 1><<<dim3(NTOK / 128, HIGH / 128, BB), blk, SM0>>>(
        HIGH, NTOK, LOW,
        WK, LOW, 0,
        XR, LOW, (long long)NTOK * LOW,
        KT, NTOK, (long long)HIGH * NTOK,
        wk_b, 1.f, 1);
    // V = x @ wv_w^T + wv_b (col bias)          [16384, 512]
    gemm_tc<0, 0><<<dim3(LOW / 128, MT / 128, 1), blk, SM0>>>(
        MT, LOW, LOW, XR, LOW, 0, WV, LOW, 0, V, LOW, 0, wv_b, 1.f, 1);

    // e[b] = QT[b] @ KT[b]^T / sqrt(HIGH)       [8][512][4096]
    gemm_tc<0, 0><<<dim3(HIGH / 128, LOW / 128, BB), blk, SM0>>>(
        LOW, HIGH, NTOK,
        QT, NTOK, (long long)LOW * NTOK,
        KT, NTOK, (long long)HIGH * NTOK,
        E, HIGH, (long long)LOW * HIGH,
        nullptr, 0.015625f, 0);

    // E <- softmax_global(E) + softmax_local(minmaxnorm(E, mask))
    attn_combine_kernel<<<dim3(LOW, BB), 256>>>(E, link);

    // x[b] = V[b] @ E[b]                        [8][2048][4096]
    gemm_tc<1, 0><<<dim3(HIGH / 128, NTOK / 128, BB), blk, SM1>>>(
        NTOK, HIGH, LOW,
        V, LOW, (long long)NTOK * LOW,
        E, HIGH, (long long)LOW * HIGH,
        X, HIGH, (long long)NTOK * HIGH,
        nullptr, 1.f, 1);

    // out = x @ o_w^T + o_b                     [16384, 4096]
    gemm_tc<0, 0><<<dim3(HIGH / 128, MT / 128, 1), blk, SM0>>>(
        MT, HIGH, HIGH, X, HIGH, 0, OW, HIGH, 0, out, HIGH, 0, o_b, 1.f, 0);
}

// round 6
// speedup vs baseline: 7.7292x; 1.9834x over previous
#include <cuda_runtime.h>
#include <cstdint>

#define BB    8
#define NTOK  2048
#define LOW   512
#define HIGH  4096

// ---------------- scratch (static device memory; no allocs allowed) -------
__device__ float g_Q[(size_t)BB * LOW * NTOK];    // QT  [b][l][n]
__device__ float g_K[(size_t)BB * HIGH * NTOK];   // KT  [b][h][n]
__device__ float g_V[(size_t)BB * NTOK * LOW];    // V   [b][n][l]
__device__ float g_E[(size_t)BB * LOW * HIGH];    // e -> combined attn
__device__ float g_T[(size_t)BB * HIGH * LOW];    // T2 = o_w @ attn^T   [b][h'][l]
// tf32-rounded copies of external inputs
__device__ float g_XR[(size_t)BB * NTOK * LOW];
__device__ float g_WQ[(size_t)LOW * LOW];
__device__ float g_WK[(size_t)HIGH * LOW];
__device__ float g_WV[(size_t)LOW * LOW];
__device__ float g_OW[(size_t)HIGH * HIGH];

// ---------------- helpers ---------------------------------------------------
__device__ __forceinline__ uint32_t smem_u32(const void* p) {
    return (uint32_t)__cvta_generic_to_shared(p);
}
__device__ __forceinline__ void cp16(uint32_t s, const void* g) {
    asm volatile("cp.async.cg.shared.global [%0], [%1], 16;" :: "r"(s), "l"(g));
}
__device__ __forceinline__ void cp_commit() {
    asm volatile("cp.async.commit_group;" ::: "memory");
}
template <int N>
__device__ __forceinline__ void cp_wait() {
    asm volatile("cp.async.wait_group %0;" :: "n"(N) : "memory");
}
__device__ __forceinline__ float tf32r(float f) {
    uint32_t r;
    asm("cvt.rna.tf32.f32 %0, %1;" : "=r"(r) : "f"(f));
    return __uint_as_float(r);
}
__device__ __forceinline__ void ldsm4(uint32_t& d0, uint32_t& d1,
                                      uint32_t& d2, uint32_t& d3, uint32_t a) {
    asm volatile("ldmatrix.sync.aligned.m8n8.x4.shared.b16 {%0,%1,%2,%3}, [%4];"
                 : "=r"(d0), "=r"(d1), "=r"(d2), "=r"(d3) : "r"(a));
}

// ---------------- tf32 rounding pass ----------------------------------------
__global__ __launch_bounds__(256) void round_tf32_kernel(
    float* __restrict__ d, const float* __restrict__ s, int n4)
{
    int i = blockIdx.x * 256 + threadIdx.x;
    if (i < n4) {
        float4 v = ((const float4*)s)[i];
        v.x = tf32r(v.x); v.y = tf32r(v.y); v.z = tf32r(v.z); v.w = tf32r(v.w);
        ((float4*)d)[i] = v;
    }
}

// ---------------- tf32 tensor-core GEMM -------------------------------------
// C[m,n] = alpha * sum_k A(m,k) * B(n,k) + bias
// A stored [M, K] (k contiguous), B stored [N, K] (k contiguous); both ldmatrix.
// BIASROW 1: bias indexed by m (row); 0: by n (col), bias may be null.
#define Bb      128
#define BK      32
#define STAGES  3

template <int BIASROW>
__global__ __launch_bounds__(256, 2) void gemm_tc(
    int M, int N, int K,
    const float* __restrict__ A, int lda, long long strideA,
    const float* __restrict__ B, int ldb, long long strideB,
    float* __restrict__ C, int ldc, long long strideC,
    const float* __restrict__ bias, float alpha, int round_out)
{
    constexpr int ATF = Bb * 36;

    extern __shared__ float sm[];
    float* sAst = sm;                       // [STAGES][ATF]
    float* sBst = sm + STAGES * ATF;        // [STAGES][ATF]

    const int tid = threadIdx.x;
    const int wid = tid >> 5;
    const int lane = tid & 31;
    const int g = lane >> 2;      // 0..7
    const int t = lane & 3;       // 0..3
    const int warp_m = wid & 1;   // 2 warps over M
    const int warp_n = wid >> 1;  // 4 warps over N
    const int lmat = lane >> 3;   // ldmatrix: which 8x8 matrix
    const int lrow = lane & 7;    // ldmatrix: row within matrix

    A += (long long)blockIdx.z * strideA;
    B += (long long)blockIdx.z * strideB;
    C += (long long)blockIdx.z * strideC;
    const int m0 = blockIdx.y * Bb;
    const int n0 = blockIdx.x * Bb;

    auto loadA = [&](int st, int k0) {
        uint32_t s0 = smem_u32(sAst + st * ATF);
#pragma unroll
        for (int r = 0; r < 4; r++) {
            int i = tid + r * 256;
            int row = i >> 3, kq = i & 7;
            cp16(s0 + (uint32_t)(row * 144 + kq * 16),
                 &A[(long long)(m0 + row) * lda + k0 + kq * 4]);
        }
    };
    auto loadB = [&](int st, int k0) {
        uint32_t s0 = smem_u32(sBst + st * ATF);
#pragma unroll
        for (int r = 0; r < 4; r++) {
            int i = tid + r * 256;
            int row = i >> 3, kq = i & 7;
            cp16(s0 + (uint32_t)(row * 144 + kq * 16),
                 &B[(long long)(n0 + row) * ldb + k0 + kq * 4]);
        }
    };

    // ldmatrix row offsets (floats), constant across iters/kk.
    int a_off[4];
#pragma unroll
    for (int mf = 0; mf < 4; mf++)
        a_off[mf] = (warp_m * 64 + mf * 16 + ((lmat & 1) << 3) + lrow) * 36
                    + ((lmat >> 1) << 2);
    int b_off[2];
#pragma unroll
    for (int nf2 = 0; nf2 < 2; nf2++)
        b_off[nf2] = (warp_n * 32 + nf2 * 16 + ((lmat >> 1) << 3) + lrow) * 36
                     + ((lmat & 1) << 2);

    float acc[4][4][4];
#pragma unroll
    for (int i = 0; i < 4; i++)
#pragma unroll
        for (int j = 0; j < 4; j++)
#pragma unroll
            for (int r = 0; r < 4; r++) acc[i][j][r] = 0.f;

    const int niter = K >> 5;

#pragma unroll
    for (int s = 0; s < STAGES - 1; s++) {
        loadA(s, s * BK);
        loadB(s, s * BK);
        cp_commit();
    }

    for (int it = 0; it < niter; it++) {
        cp_wait<STAGES - 2>();
        __syncthreads();

        {
            int ns = it + STAGES - 1;
            if (ns < niter) {
                int st = ns % STAGES;
                loadA(st, ns * BK);
                loadB(st, ns * BK);
            }
            cp_commit();
        }

        const int stg = it % STAGES;
        const uint32_t sa = smem_u32(sAst + stg * ATF);
        const uint32_t sb = smem_u32(sBst + stg * ATF);

#pragma unroll
        for (int kk = 0; kk < BK; kk += 8) {
            uint32_t ua[4][4], ub[4][2];
#pragma unroll
            for (int mf = 0; mf < 4; mf++)
                ldsm4(ua[mf][0], ua[mf][1], ua[mf][2], ua[mf][3],
                      sa + (uint32_t)(a_off[mf] + kk) * 4u);
#pragma unroll
            for (int nf2 = 0; nf2 < 2; nf2++)
                ldsm4(ub[nf2 * 2][0], ub[nf2 * 2][1],
                      ub[nf2 * 2 + 1][0], ub[nf2 * 2 + 1][1],
                      sb + (uint32_t)(b_off[nf2] + kk) * 4u);
#pragma unroll
            for (int mf = 0; mf < 4; mf++)
#pragma unroll
                for (int nf = 0; nf < 4; nf++) {
                    asm volatile(
                        "mma.sync.aligned.m16n8k8.row.col.f32.tf32.tf32.f32 "
                        "{%0,%1,%2,%3}, {%4,%5,%6,%7}, {%8,%9}, {%0,%1,%2,%3};"
                        : "+f"(acc[mf][nf][0]), "+f"(acc[mf][nf][1]),
                          "+f"(acc[mf][nf][2]), "+f"(acc[mf][nf][3])
                        : "r"(ua[mf][0]), "r"(ua[mf][1]), "r"(ua[mf][2]), "r"(ua[mf][3]),
                          "r"(ub[nf][0]), "r"(ub[nf][1]));
                }
        }
    }

    // ---- epilogue ----
#pragma unroll
    for (int mf = 0; mf < 4; mf++) {
        const int row = m0 + warp_m * 64 + mf * 16 + g;
        float br0 = 0.f, br1 = 0.f;
        if (BIASROW) { br0 = bias[row]; br1 = bias[row + 8]; }
#pragma unroll
        for (int nf = 0; nf < 4; nf++) {
            const int col = n0 + warp_n * 32 + nf * 8 + t * 2;
            float b0 = br0, b1 = br0, c0 = br1, c1 = br1;
            if (!BIASROW && bias) {
                b0 = bias[col]; b1 = bias[col + 1]; c0 = b0; c1 = b1;
            } else if (!BIASROW) {
                b0 = b1 = c0 = c1 = 0.f;
            }
            float v00 = acc[mf][nf][0] * alpha + b0;
            float v01 = acc[mf][nf][1] * alpha + b1;
            float v10 = acc[mf][nf][2] * alpha + c0;
            float v11 = acc[mf][nf][3] * alpha + c1;
            if (round_out) {
                v00 = tf32r(v00); v01 = tf32r(v01);
                v10 = tf32r(v10); v11 = tf32r(v11);
            }
            *(float2*)&C[(long long)row * ldc + col] = make_float2(v00, v01);
            *(float2*)&C[(long long)(row + 8) * ldc + col] = make_float2(v10, v11);
        }
    }
}

// ---------------- combined softmax(e) + softmax(minmaxnorm(e,mask)) --------
__device__ __forceinline__ float warpMax(float v) {
#pragma unroll
    for (int o = 16; o > 0; o >>= 1) v = fmaxf(v, __shfl_xor_sync(0xffffffffu, v, o));
    return v;
}
__device__ __forceinline__ float warpMin(float v) {
#pragma unroll
    for (int o = 16; o > 0; o >>= 1) v = fminf(v, __shfl_xor_sync(0xffffffffu, v, o));
    return v;
}
__device__ __forceinline__ float warpSum(float v) {
#pragma unroll
    for (int o = 16; o > 0; o >>= 1) v += __shfl_xor_sync(0xffffffffu, v, o);
    return v;
}

__global__ __launch_bounds__(256) void attn_combine_kernel(
    float* __restrict__ E, const int* __restrict__ linkage)
{
    const int H = HIGH;
    const int l = blockIdx.x;
    const int b = blockIdx.y;
    float* row = E + ((long long)b * LOW + l) * H;
    const int* mrow = linkage + (long long)l * H;

    __shared__ float se[HIGH];
    __shared__ unsigned char smk[HIGH];
    __shared__ float bufg[8], bufn[8], bufx[8], bufs1[8], bufs2[8];

    const int tid = threadIdx.x;
    const int lane = tid & 31, wid = tid >> 5;
    const float BIGV = 9.0e15f;

    float gmax = -3.0e38f, mn = BIGV, mx = -BIGV;
    for (int h = tid; h < H; h += 256) {
        float v = row[h];
        int m = mrow[h];
        se[h] = v;
        smk[h] = (unsigned char)(m > 0);
        gmax = fmaxf(gmax, v);
        if (m > 0) { mn = fminf(mn, v); mx = fmaxf(mx, v); }
    }
    gmax = warpMax(gmax); mn = warpMin(mn); mx = warpMax(mx);
    if (lane == 0) { bufg[wid] = gmax; bufn[wid] = mn; bufx[wid] = mx; }
    __syncthreads();
    float GM = bufg[0], MN = bufn[0], MX = bufx[0];
#pragma unroll
    for (int i = 1; i < 8; i++) {
        GM = fmaxf(GM, bufg[i]); MN = fminf(MN, bufn[i]); MX = fmaxf(MX, bufx[i]);
    }

    float den = MX - MN;
    if (den == 0.f) den = 1e-6f;
    const float rden = 1.f / den;
    const float lmax = (MX - MN) * rden;

    float gsum = 0.f, lsum = 0.f;
    for (int h = tid; h < H; h += 256) {
        float v = se[h];
        gsum += __expf(v - GM);
        if (smk[h]) lsum += __expf((v - MN) * rden - lmax);
    }
    gsum = warpSum(gsum); lsum = warpSum(lsum);
    if (lane == 0) { bufs1[wid] = gsum; bufs2[wid] = lsum; }
    __syncthreads();
    float GS = 0.f, LS = 0.f;
#pragma unroll
    for (int i = 0; i < 8; i++) { GS += bufs1[i]; LS += bufs2[i]; }
    const float rg = 1.f / GS, rl = 1.f / LS;

    for (int h = tid; h < H; h += 256) {
        float v = se[h];
        float o = __expf(v - GM) * rg;
        if (smk[h]) o += __expf((v - MN) * rden - lmax) * rl;
        row[h] = tf32r(o);   // next consumer is a tf32 GEMM
    }
}

// ---------------- launch ----------------------------------------------------
extern "C" void kernel_launch(void* const* d_in, const int* in_sizes, int n_in,
                              void* d_out, int out_size)
{
    const float* x    = (const float*)d_in[0];
    const int*   link = (const int*)  d_in[1];
    const float* wq_w = (const float*)d_in[2];
    const float* wq_b = (const float*)d_in[3];
    const float* wk_w = (const float*)d_in[4];
    const float* wk_b = (const float*)d_in[5];
    const float* wv_w = (const float*)d_in[6];
    const float* wv_b = (const float*)d_in[7];
    const float* o_w  = (const float*)d_in[8];
    const float* o_b  = (const float*)d_in[9];
    float* out = (float*)d_out;

    float *QT, *KT, *V, *E, *T2, *XR, *WQ, *WK, *WV, *OW;
    cudaGetSymbolAddress((void**)&QT, g_Q);
    cudaGetSymbolAddress((void**)&KT, g_K);
    cudaGetSymbolAddress((void**)&V,  g_V);
    cudaGetSymbolAddress((void**)&E,  g_E);
    cudaGetSymbolAddress((void**)&T2, g_T);
    cudaGetSymbolAddress((void**)&XR, g_XR);
    cudaGetSymbolAddress((void**)&WQ, g_WQ);
    cudaGetSymbolAddress((void**)&WK, g_WK);
    cudaGetSymbolAddress((void**)&WV, g_WV);
    cudaGetSymbolAddress((void**)&OW, g_OW);

    constexpr int SMG = STAGES * 2 * (Bb * 36) * 4;    // 110592
    cudaFuncSetAttribute(gemm_tc<0>, cudaFuncAttributeMaxDynamicSharedMemorySize, SMG);
    cudaFuncSetAttribute(gemm_tc<1>, cudaFuncAttributeMaxDynamicSharedMemorySize, SMG);

    const int MT = BB * NTOK;
    dim3 blk(256);

    // --- pre-round external inputs to tf32 ---
    auto launch_round = [&](float* d, const float* s, long long n) {
        int n4 = (int)(n >> 2);
        round_tf32_kernel<<<(n4 + 255) / 256, 256>>>(d, s, n4);
    };
    launch_round(XR, x,    (long long)MT * LOW);
    launch_round(WQ, wq_w, (long long)LOW * LOW);
    launch_round(WK, wk_w, (long long)HIGH * LOW);
    launch_round(WV, wv_w, (long long)LOW * LOW);
    launch_round(OW, o_w,  (long long)HIGH * HIGH);

    // QT[b] = wq @ x[b]^T + wq_b (row bias)     [8][512][2048]
    gemm_tc<1><<<dim3(NTOK / 128, LOW / 128, BB), blk, SMG>>>(
        LOW, NTOK, LOW,
        WQ, LOW, 0,
        XR, LOW, (long long)NTOK * LOW,
        QT, NTOK, (long long)LOW * NTOK,
        wq_b, 1.f, 1);
    // KT[b] = wk @ x[b]^T + wk_b (row bias)     [8][4096][2048]
    gemm_tc<1><<<dim3(NTOK / 128, HIGH / 128, BB), blk, SMG>>>(
        HIGH, NTOK, LOW,
        WK, LOW, 0,
        XR, LOW, (long long)NTOK * LOW,
        KT, NTOK, (long long)HIGH * NTOK,
        wk_b, 1.f, 1);
    // V = x @ wv_w^T + wv_b (col bias)          [16384, 512]
    gemm_tc<0><<<dim3(LOW / 128, MT / 128, 1), blk, SMG>>>(
        MT, LOW, LOW, XR, LOW, 0, WV, LOW, 0, V, LOW, 0, wv_b, 1.f, 1);

    // e[b] = QT[b] @ KT[b]^T / sqrt(HIGH)       [8][512][4096]
    gemm_tc<0><<<dim3(HIGH / 128, LOW / 128, BB), blk, SMG>>>(
        LOW, HIGH, NTOK,
        QT, NTOK, (long long)LOW * NTOK,
        KT, NTOK, (long long)HIGH * NTOK,
        E, HIGH, (long long)LOW * HIGH,
        nullptr, 0.015625f, 0);

    // E <- softmax_global(E) + softmax_local(minmaxnorm(E, mask))
    attn_combine_kernel<<<dim3(LOW, BB), 256>>>(E, link);

    // T2[b] = o_w @ attn[b]^T                   [8][4096][512]
    // A = OW [h', h] k-contig;  B = E[b] [l, h] k-contig
    gemm_tc<0><<<dim3(LOW / 128, HIGH / 128, BB), blk, SMG>>>(
        HIGH, LOW, HIGH,
        OW, HIGH, 0,
        E, HIGH, (long long)LOW * HIGH,
        T2, LOW, (long long)HIGH * LOW,
        nullptr, 1.f, 1);

    // out[b] = V[b] @ T2[b]^T + o_b (col bias)  [8][2048][4096]
    gemm_tc<0><<<dim3(HIGH / 128, NTOK / 128, BB), blk, SMG>>>(
        NTOK, HIGH, LOW,
        V, LOW, (long long)NTOK * LOW,
        T2, LOW, (long long)HIGH * LOW,
        out, HIGH, (long long)NTOK * HIGH,
        o_b, 1.f, 0);
}

// round 7
// speedup vs baseline: 10.2737x; 1.3292x over previous
#include <cuda_runtime.h>
#include <cstdint>

#define BB    8
#define NTOK  2048
#define LOW   512
#define HIGH  4096

// ---------------- scratch (static device memory; no allocs allowed) -------
__device__ float g_XT[(size_t)BB * LOW * NTOK];   // x^T       [b][l][n]
__device__ float g_G [(size_t)BB * LOW * LOW];    // x^T x     [b][l1][l2]
__device__ float g_M1[(size_t)BB * LOW * LOW];    // wq G      [b][lq][l2]
__device__ float g_V [(size_t)BB * NTOK * LOW];   // V         [b][n][l]
__device__ float g_E [(size_t)BB * LOW * HIGH];   // e -> combined attn
__device__ float g_T [(size_t)BB * HIGH * LOW];   // T2 = o_w @ attn^T
__device__ float g_S [(size_t)BB * LOW];          // col sums of x
__device__ float g_U [(size_t)BB * HIGH];         // wk @ s
__device__ float g_Vv[(size_t)BB * LOW];          // wq @ s
// tf32-rounded copies of external inputs
__device__ float g_XR[(size_t)BB * NTOK * LOW];
__device__ float g_WQ[(size_t)LOW * LOW];
__device__ float g_WK[(size_t)HIGH * LOW];
__device__ float g_WV[(size_t)LOW * LOW];
__device__ float g_OW[(size_t)HIGH * HIGH];

// ---------------- helpers ---------------------------------------------------
__device__ __forceinline__ uint32_t smem_u32(const void* p) {
    return (uint32_t)__cvta_generic_to_shared(p);
}
__device__ __forceinline__ void cp16(uint32_t s, const void* g) {
    asm volatile("cp.async.cg.shared.global [%0], [%1], 16;" :: "r"(s), "l"(g));
}
__device__ __forceinline__ void cp_commit() {
    asm volatile("cp.async.commit_group;" ::: "memory");
}
template <int N>
__device__ __forceinline__ void cp_wait() {
    asm volatile("cp.async.wait_group %0;" :: "n"(N) : "memory");
}
__device__ __forceinline__ float tf32r(float f) {
    uint32_t r;
    asm("cvt.rna.tf32.f32 %0, %1;" : "=r"(r) : "f"(f));
    return __uint_as_float(r);
}
__device__ __forceinline__ void ldsm4(uint32_t& d0, uint32_t& d1,
                                      uint32_t& d2, uint32_t& d3, uint32_t a) {
    asm volatile("ldmatrix.sync.aligned.m8n8.x4.shared.b16 {%0,%1,%2,%3}, [%4];"
                 : "=r"(d0), "=r"(d1), "=r"(d2), "=r"(d3) : "r"(a));
}
__device__ __forceinline__ float warpSum(float v) {
#pragma unroll
    for (int o = 16; o > 0; o >>= 1) v += __shfl_xor_sync(0xffffffffu, v, o);
    return v;
}
__device__ __forceinline__ float warpMax(float v) {
#pragma unroll
    for (int o = 16; o > 0; o >>= 1) v = fmaxf(v, __shfl_xor_sync(0xffffffffu, v, o));
    return v;
}
__device__ __forceinline__ float warpMin(float v) {
#pragma unroll
    for (int o = 16; o > 0; o >>= 1) v = fminf(v, __shfl_xor_sync(0xffffffffu, v, o));
    return v;
}

// ---------------- tf32 rounding pass ----------------------------------------
__global__ __launch_bounds__(256) void round_tf32_kernel(
    float* __restrict__ d, const float* __restrict__ s, int n4)
{
    int i = blockIdx.x * 256 + threadIdx.x;
    if (i < n4) {
        float4 v = ((const float4*)s)[i];
        v.x = tf32r(v.x); v.y = tf32r(v.y); v.z = tf32r(v.z); v.w = tf32r(v.w);
        ((float4*)d)[i] = v;
    }
}

// ---------------- transpose: XT[b] = XR[b]^T ---------------------------------
__global__ __launch_bounds__(256) void transpose_kernel(
    float* __restrict__ dst, const float* __restrict__ src)
{
    __shared__ float tile[32][33];
    const int b = blockIdx.z;
    const int n0 = blockIdx.x * 32, l0 = blockIdx.y * 32;
    const float* s = src + (size_t)b * NTOK * LOW;
    float* d = dst + (size_t)b * LOW * NTOK;
    const int tx = threadIdx.x, ty = threadIdx.y;   // 32 x 8
#pragma unroll
    for (int r = 0; r < 32; r += 8)
        tile[ty + r][tx] = s[(size_t)(n0 + ty + r) * LOW + l0 + tx];
    __syncthreads();
#pragma unroll
    for (int r = 0; r < 32; r += 8)
        d[(size_t)(l0 + ty + r) * NTOK + n0 + tx] = tile[tx][ty + r];
}

// ---------------- column sums: s[b][l] = sum_n x[b][n][l] --------------------
__global__ __launch_bounds__(256) void colsum_kernel(
    float* __restrict__ s, const float* __restrict__ x)
{
    const int b = blockIdx.y;
    const int l = blockIdx.x * 256 + threadIdx.x;
    const float* xp = x + (size_t)b * NTOK * LOW + l;
    float acc = 0.f;
    for (int n = 0; n < NTOK; n++) acc += xp[(size_t)n * LOW];
    s[b * LOW + l] = acc;
}

// ---------------- matvec: out[b][m] = dot(W[m,:], s[b]) ----------------------
__global__ __launch_bounds__(256) void matvec_kernel(
    float* __restrict__ out, const float* __restrict__ W,
    const float* __restrict__ s, int rows)
{
    const int b = blockIdx.y;
    const int row = blockIdx.x * 8 + (threadIdx.x >> 5);
    const int lane = threadIdx.x & 31;
    if (row >= rows) return;
    const float* w = W + (size_t)row * LOW;
    const float* sv = s + b * LOW;
    float acc = 0.f;
    for (int i = lane; i < LOW; i += 32) acc += w[i] * sv[i];
    acc = warpSum(acc);
    if (lane == 0) out[(size_t)b * rows + row] = acc;
}

// ---------------- tf32 tensor-core GEMM -------------------------------------
// C[m,n] = alpha * sum_k A(m,k) * B(n,k) + bias
// A stored [M, K] (k contiguous), B stored [N, K] (k contiguous); both ldmatrix.
// BIASROW 1: bias indexed by m (row); 0: by n (col), bias may be null.
#define Bb      128
#define BK      32
#define STAGES  3

template <int BIASROW>
__global__ __launch_bounds__(256, 2) void gemm_tc(
    int M, int N, int K,
    const float* __restrict__ A, int lda, long long strideA,
    const float* __restrict__ B, int ldb, long long strideB,
    float* __restrict__ C, int ldc, long long strideC,
    const float* __restrict__ bias, float alpha, int round_out)
{
    constexpr int ATF = Bb * 36;

    extern __shared__ float sm[];
    float* sAst = sm;
    float* sBst = sm + STAGES * ATF;

    const int tid = threadIdx.x;
    const int wid = tid >> 5;
    const int lane = tid & 31;
    const int g = lane >> 2;
    const int t = lane & 3;
    const int warp_m = wid & 1;
    const int warp_n = wid >> 1;
    const int lmat = lane >> 3;
    const int lrow = lane & 7;

    A += (long long)blockIdx.z * strideA;
    B += (long long)blockIdx.z * strideB;
    C += (long long)blockIdx.z * strideC;
    const int m0 = blockIdx.y * Bb;
    const int n0 = blockIdx.x * Bb;

    auto loadA = [&](int st, int k0) {
        uint32_t s0 = smem_u32(sAst + st * ATF);
#pragma unroll
        for (int r = 0; r < 4; r++) {
            int i = tid + r * 256;
            int row = i >> 3, kq = i & 7;
            cp16(s0 + (uint32_t)(row * 144 + kq * 16),
                 &A[(long long)(m0 + row) * lda + k0 + kq * 4]);
        }
    };
    auto loadB = [&](int st, int k0) {
        uint32_t s0 = smem_u32(sBst + st * ATF);
#pragma unroll
        for (int r = 0; r < 4; r++) {
            int i = tid + r * 256;
            int row = i >> 3, kq = i & 7;
            cp16(s0 + (uint32_t)(row * 144 + kq * 16),
                 &B[(long long)(n0 + row) * ldb + k0 + kq * 4]);
        }
    };

    int a_off[4];
#pragma unroll
    for (int mf = 0; mf < 4; mf++)
        a_off[mf] = (warp_m * 64 + mf * 16 + ((lmat & 1) << 3) + lrow) * 36
                    + ((lmat >> 1) << 2);
    int b_off[2];
#pragma unroll
    for (int nf2 = 0; nf2 < 2; nf2++)
        b_off[nf2] = (warp_n * 32 + nf2 * 16 + ((lmat >> 1) << 3) + lrow) * 36
                     + ((lmat & 1) << 2);

    float acc[4][4][4];
#pragma unroll
    for (int i = 0; i < 4; i++)
#pragma unroll
        for (int j = 0; j < 4; j++)
#pragma unroll
            for (int r = 0; r < 4; r++) acc[i][j][r] = 0.f;

    const int niter = K >> 5;

#pragma unroll
    for (int s = 0; s < STAGES - 1; s++) {
        loadA(s, s * BK);
        loadB(s, s * BK);
        cp_commit();
    }

    for (int it = 0; it < niter; it++) {
        cp_wait<STAGES - 2>();
        __syncthreads();

        {
            int ns = it + STAGES - 1;
            if (ns < niter) {
                int st = ns % STAGES;
                loadA(st, ns * BK);
                loadB(st, ns * BK);
            }
            cp_commit();
        }

        const int stg = it % STAGES;
        const uint32_t sa = smem_u32(sAst + stg * ATF);
        const uint32_t sb = smem_u32(sBst + stg * ATF);

#pragma unroll
        for (int kk = 0; kk < BK; kk += 8) {
            uint32_t ua[4][4], ub[4][2];
#pragma unroll
            for (int mf = 0; mf < 4; mf++)
                ldsm4(ua[mf][0], ua[mf][1], ua[mf][2], ua[mf][3],
                      sa + (uint32_t)(a_off[mf] + kk) * 4u);
#pragma unroll
            for (int nf2 = 0; nf2 < 2; nf2++)
                ldsm4(ub[nf2 * 2][0], ub[nf2 * 2][1],
                      ub[nf2 * 2 + 1][0], ub[nf2 * 2 + 1][1],
                      sb + (uint32_t)(b_off[nf2] + kk) * 4u);
#pragma unroll
            for (int mf = 0; mf < 4; mf++)
#pragma unroll
                for (int nf = 0; nf < 4; nf++) {
                    asm volatile(
                        "mma.sync.aligned.m16n8k8.row.col.f32.tf32.tf32.f32 "
                        "{%0,%1,%2,%3}, {%4,%5,%6,%7}, {%8,%9}, {%0,%1,%2,%3};"
                        : "+f"(acc[mf][nf][0]), "+f"(acc[mf][nf][1]),
                          "+f"(acc[mf][nf][2]), "+f"(acc[mf][nf][3])
                        : "r"(ua[mf][0]), "r"(ua[mf][1]), "r"(ua[mf][2]), "r"(ua[mf][3]),
                          "r"(ub[nf][0]), "r"(ub[nf][1]));
                }
        }
    }

    // ---- epilogue ----
#pragma unroll
    for (int mf = 0; mf < 4; mf++) {
        const int row = m0 + warp_m * 64 + mf * 16 + g;
        float br0 = 0.f, br1 = 0.f;
        if (BIASROW) { br0 = bias[row]; br1 = bias[row + 8]; }
#pragma unroll
        for (int nf = 0; nf < 4; nf++) {
            const int col = n0 + warp_n * 32 + nf * 8 + t * 2;
            float b0 = br0, b1 = br0, c0 = br1, c1 = br1;
            if (!BIASROW && bias) {
                b0 = bias[col]; b1 = bias[col + 1]; c0 = b0; c1 = b1;
            } else if (!BIASROW) {
                b0 = b1 = c0 = c1 = 0.f;
            }
            float v00 = acc[mf][nf][0] * alpha + b0;
            float v01 = acc[mf][nf][1] * alpha + b1;
            float v10 = acc[mf][nf][2] * alpha + c0;
            float v11 = acc[mf][nf][3] * alpha + c1;
            if (round_out) {
                v00 = tf32r(v00); v01 = tf32r(v01);
                v10 = tf32r(v10); v11 = tf32r(v11);
            }
            *(float2*)&C[(long long)row * ldc + col] = make_float2(v00, v01);
            *(float2*)&C[(long long)(row + 8) * ldc + col] = make_float2(v10, v11);
        }
    }
}

// ---------------- combined softmax + bias rank-1 corrections ----------------
// row(b,l): e_full[h] = E[l,h] + alpha*( bq[l]*u[b][h] + (v[b][l]+NTOK*bq[l])*bk[h] )
__global__ __launch_bounds__(256) void attn_combine_kernel(
    float* __restrict__ E, const int* __restrict__ linkage,
    const float* __restrict__ u, const float* __restrict__ vv,
    const float* __restrict__ bq, const float* __restrict__ bk)
{
    const int H = HIGH;
    const int l = blockIdx.x;
    const int b = blockIdx.y;
    float* row = E + ((long long)b * LOW + l) * H;
    const int* mrow = linkage + (long long)l * H;
    const float* urow = u + (long long)b * HIGH;

    __shared__ float se[HIGH];
    __shared__ unsigned char smk[HIGH];
    __shared__ float bufg[8], bufn[8], bufx[8], bufs1[8], bufs2[8];

    const int tid = threadIdx.x;
    const int lane = tid & 31, wid = tid >> 5;
    const float BIGV = 9.0e15f;
    const float ALPHA = 0.015625f;

    const float cq = bq[l];
    const float ck = vv[b * LOW + l] + (float)NTOK * cq;

    float gmax = -3.0e38f, mn = BIGV, mx = -BIGV;
    for (int h = tid; h < H; h += 256) {
        float v = row[h] + ALPHA * (cq * urow[h] + ck * bk[h]);
        int m = mrow[h];
        se[h] = v;
        smk[h] = (unsigned char)(m > 0);
        gmax = fmaxf(gmax, v);
        if (m > 0) { mn = fminf(mn, v); mx = fmaxf(mx, v); }
    }
    gmax = warpMax(gmax); mn = warpMin(mn); mx = warpMax(mx);
    if (lane == 0) { bufg[wid] = gmax; bufn[wid] = mn; bufx[wid] = mx; }
    __syncthreads();
    float GM = bufg[0], MN = bufn[0], MX = bufx[0];
#pragma unroll
    for (int i = 1; i < 8; i++) {
        GM = fmaxf(GM, bufg[i]); MN = fminf(MN, bufn[i]); MX = fmaxf(MX, bufx[i]);
    }

    float den = MX - MN;
    if (den == 0.f) den = 1e-6f;
    const float rden = 1.f / den;
    const float lmax = (MX - MN) * rden;

    float gsum = 0.f, lsum = 0.f;
    for (int h = tid; h < H; h += 256) {
        float v = se[h];
        gsum += __expf(v - GM);
        if (smk[h]) lsum += __expf((v - MN) * rden - lmax);
    }
    gsum = warpSum(gsum); lsum = warpSum(lsum);
    if (lane == 0) { bufs1[wid] = gsum; bufs2[wid] = lsum; }
    __syncthreads();
    float GS = 0.f, LS = 0.f;
#pragma unroll
    for (int i = 0; i < 8; i++) { GS += bufs1[i]; LS += bufs2[i]; }
    const float rg = 1.f / GS, rl = 1.f / LS;

    for (int h = tid; h < H; h += 256) {
        float v = se[h];
        float o = __expf(v - GM) * rg;
        if (smk[h]) o += __expf((v - MN) * rden - lmax) * rl;
        row[h] = tf32r(o);   // next consumer is a tf32 GEMM
    }
}

// ---------------- launch ----------------------------------------------------
extern "C" void kernel_launch(void* const* d_in, const int* in_sizes, int n_in,
                              void* d_out, int out_size)
{
    const float* x    = (const float*)d_in[0];
    const int*   link = (const int*)  d_in[1];
    const float* wq_w = (const float*)d_in[2];
    const float* wq_b = (const float*)d_in[3];
    const float* wk_w = (const float*)d_in[4];
    const float* wk_b = (const float*)d_in[5];
    const float* wv_w = (const float*)d_in[6];
    const float* wv_b = (const float*)d_in[7];
    const float* o_w  = (const float*)d_in[8];
    const float* o_b  = (const float*)d_in[9];
    float* out = (float*)d_out;

    float *XT, *G, *M1, *V, *E, *T2, *S, *U, *Vv;
    float *XR, *WQ, *WK, *WV, *OW;
    cudaGetSymbolAddress((void**)&XT, g_XT);
    cudaGetSymbolAddress((void**)&G,  g_G);
    cudaGetSymbolAddress((void**)&M1, g_M1);
    cudaGetSymbolAddress((void**)&V,  g_V);
    cudaGetSymbolAddress((void**)&E,  g_E);
    cudaGetSymbolAddress((void**)&T2, g_T);
    cudaGetSymbolAddress((void**)&S,  g_S);
    cudaGetSymbolAddress((void**)&U,  g_U);
    cudaGetSymbolAddress((void**)&Vv, g_Vv);
    cudaGetSymbolAddress((void**)&XR, g_XR);
    cudaGetSymbolAddress((void**)&WQ, g_WQ);
    cudaGetSymbolAddress((void**)&WK, g_WK);
    cudaGetSymbolAddress((void**)&WV, g_WV);
    cudaGetSymbolAddress((void**)&OW, g_OW);

    constexpr int SMG = STAGES * 2 * (Bb * 36) * 4;    // 110592
    cudaFuncSetAttribute(gemm_tc<0>, cudaFuncAttributeMaxDynamicSharedMemorySize, SMG);
    cudaFuncSetAttribute(gemm_tc<1>, cudaFuncAttributeMaxDynamicSharedMemorySize, SMG);

    const int MT = BB * NTOK;
    dim3 blk(256);

    // --- pre-round external inputs to tf32 ---
    auto launch_round = [&](float* d, const float* s, long long n) {
        int n4 = (int)(n >> 2);
        round_tf32_kernel<<<(n4 + 255) / 256, 256>>>(d, s, n4);
    };
    launch_round(XR, x,    (long long)MT * LOW);
    launch_round(WQ, wq_w, (long long)LOW * LOW);
    launch_round(WK, wk_w, (long long)HIGH * LOW);
    launch_round(WV, wv_w, (long long)LOW * LOW);
    launch_round(OW, o_w,  (long long)HIGH * HIGH);

    // --- bias-correction ingredients (exact, fp32) ---
    colsum_kernel<<<dim3(LOW / 256, BB), 256>>>(S, XR);
    matvec_kernel<<<dim3(HIGH / 8, BB), 256>>>(U, wk_w, S, HIGH);
    matvec_kernel<<<dim3(LOW / 8, BB), 256>>>(Vv, wq_w, S, LOW);

    // --- XT[b] = XR[b]^T ---
    transpose_kernel<<<dim3(NTOK / 32, LOW / 32, BB), dim3(32, 8)>>>(XT, XR);

    // G[b] = x^T x          [8][512][512]  (symmetric)
    gemm_tc<0><<<dim3(LOW / 128, LOW / 128, BB), blk, SMG>>>(
        LOW, LOW, NTOK,
        XT, NTOK, (long long)LOW * NTOK,
        XT, NTOK, (long long)LOW * NTOK,
        G, LOW, (long long)LOW * LOW,
        nullptr, 1.f, 1);

    // M1[b] = wq @ G[b]     [8][512][512]  (uses G symmetry for B operand)
    gemm_tc<0><<<dim3(LOW / 128, LOW / 128, BB), blk, SMG>>>(
        LOW, LOW, LOW,
        WQ, LOW, 0,
        G, LOW, (long long)LOW * LOW,
        M1, LOW, (long long)LOW * LOW,
        nullptr, 1.f, 1);

    // e[b] = M1[b] @ wk^T / sqrt(HIGH)     [8][512][4096]
    gemm_tc<0><<<dim3(HIGH / 128, LOW / 128, BB), blk, SMG>>>(
        LOW, HIGH, LOW,
        M1, LOW, (long long)LOW * LOW,
        WK, LOW, 0,
        E, HIGH, (long long)LOW * HIGH,
        nullptr, 0.015625f, 0);

    // V = x @ wv_w^T + wv_b (col bias)     [16384, 512]
    gemm_tc<0><<<dim3(LOW / 128, MT / 128, 1), blk, SMG>>>(
        MT, LOW, LOW, XR, LOW, 0, WV, LOW, 0, V, LOW, 0, wv_b, 1.f, 1);

    // E <- softmax_global + softmax_local (with rank-1 bias corrections)
    attn_combine_kernel<<<dim3(LOW, BB), 256>>>(E, link, U, Vv, wq_b, wk_b);

    // T2[b] = o_w @ attn[b]^T              [8][4096][512]
    gemm_tc<0><<<dim3(LOW / 128, HIGH / 128, BB), blk, SMG>>>(
        HIGH, LOW, HIGH,
        OW, HIGH, 0,
        E, HIGH, (long long)LOW * HIGH,
        T2, LOW, (long long)HIGH * LOW,
        nullptr, 1.f, 1);

    // out[b] = V[b] @ T2[b]^T + o_b (col bias)   [8][2048][4096]
    gemm_tc<0><<<dim3(HIGH / 128, NTOK / 128, BB), blk, SMG>>>(
        NTOK, HIGH, LOW,
        V, LOW, (long long)NTOK * LOW,
        T2, LOW, (long long)HIGH * LOW,
        out, HIGH, (long long)NTOK * HIGH,
        o_b, 1.f, 0);
}